// round 13
// baseline (speedup 1.0000x reference)
#include <cuda_runtime.h>
#include <cuda_fp16.h>
#include <cstdint>

#define D_MODEL 1024
#define NHEAD 16
#define HEAD_DIM 64
#define BATCH 4
#define SEQ 2048
#define MTOK (BATCH*SEQ)   // 8192

// ---------------- scratch (static device globals: allocation-free) ----------
__device__ __align__(256) __half g_q[(size_t)BATCH*NHEAD*SEQ*HEAD_DIM];   // [B,H,S,Dh]
__device__ __align__(256) __half g_k[(size_t)BATCH*NHEAD*SEQ*HEAD_DIM];   // [B,H,S,Dh]
__device__ __align__(256) __half g_v[(size_t)BATCH*NHEAD*SEQ*HEAD_DIM];   // [B,H,Dh,S] TRANSPOSED
__device__ __align__(256) __half g_ctx[(size_t)MTOK*D_MODEL];             // [B,S,D]
__device__ __align__(256) __half g_x[(size_t)MTOK*D_MODEL];               // [M][K]
__device__ __align__(256) __half g_wqkv[(size_t)3*D_MODEL*D_MODEL];       // [N][K] transposed
__device__ __align__(256) __half g_wout[(size_t)D_MODEL*D_MODEL];         // [N][K] transposed

// ---------------- helpers ---------------------------------------------------
__device__ __forceinline__ float ex2(float x) {
    float y;
    asm("ex2.approx.f32 %0, %1;" : "=f"(y) : "f"(x));
    return y;
}
__device__ __forceinline__ uint32_t sa(const void* p) {
    return (uint32_t)__cvta_generic_to_shared(p);
}
__device__ __forceinline__ void cpa16(uint32_t dst, const void* src) {
    asm volatile("cp.async.cg.shared.global [%0], [%1], 16;\n" :: "r"(dst), "l"(src));
}
#define CP_COMMIT asm volatile("cp.async.commit_group;\n" ::: "memory")
#define CP_WAIT1  asm volatile("cp.async.wait_group 1;\n" ::: "memory")

__device__ __forceinline__ uint32_t h2u(float a, float b) {
    __half2 h = __floats2half2_rn(a, b);
    return *reinterpret_cast<uint32_t*>(&h);
}
__device__ __forceinline__ void ldsm4(uint32_t* r, uint32_t addr) {
    asm volatile("ldmatrix.sync.aligned.m8n8.x4.shared.b16 {%0,%1,%2,%3}, [%4];"
                 : "=r"(r[0]), "=r"(r[1]), "=r"(r[2]), "=r"(r[3]) : "r"(addr));
}

// D(16x8,f32) += A(16x16 f16,row) * B(16x8 f16,col)
__device__ __forceinline__ void mma16(float* c, const uint32_t* a, const uint32_t* b) {
    asm volatile(
        "mma.sync.aligned.m16n8k16.row.col.f32.f16.f16.f32 "
        "{%0,%1,%2,%3}, {%4,%5,%6,%7}, {%8,%9}, {%0,%1,%2,%3};\n"
        : "+f"(c[0]), "+f"(c[1]), "+f"(c[2]), "+f"(c[3])
        : "r"(a[0]), "r"(a[1]), "r"(a[2]), "r"(a[3]), "r"(b[0]), "r"(b[1]));
}

// ---------------- prep kernels ----------------------------------------------
__global__ void round_h(const float* __restrict__ src, __half* __restrict__ dst, int n4)
{
    int stride = gridDim.x * blockDim.x;
    for (int i = blockIdx.x * blockDim.x + threadIdx.x; i < n4; i += stride) {
        float4 v = reinterpret_cast<const float4*>(src)[i];
        uint2 o = make_uint2(h2u(v.x, v.y), h2u(v.z, v.w));
        reinterpret_cast<uint2*>(dst)[i] = o;
    }
}

// W[K][N] fp32 -> Wt[N][K] fp16. grid (N/32, K/32), block (32,8).
__global__ void transpose_h(const float* __restrict__ src, __half* __restrict__ dst,
                            int Kdim, int Ndim)
{
    __shared__ __half ts[32][33];
    int n0 = blockIdx.x * 32, k0 = blockIdx.y * 32;
    int tx = threadIdx.x, ty = threadIdx.y;
#pragma unroll
    for (int r = 0; r < 4; r++)
        ts[ty + 8 * r][tx] = __float2half_rn(src[(size_t)(k0 + ty + 8 * r) * Ndim + n0 + tx]);
    __syncthreads();
#pragma unroll
    for (int r = 0; r < 4; r++)
        dst[(size_t)(n0 + ty + 8 * r) * Kdim + k0 + tx] = ts[tx][ty + 8 * r];
}

// ---------------- GEMM: C[M,N] = A[M,K] @ Wt[N,K]^T + bias (fp16 MMA) -------
// 256x128 CTA tile (64x64 warp tiles, 4x2 grid), k-tile 64, 3-stage cp.async,
// register-double-buffered ldmatrix fragments. 1 CTA/SM, high-ILP warps.
#define GPB 144                     // smem pitch bytes (72 halves)
#define ATB (256 * GPB)             // A tile: 36864 B
#define WTB (128 * GPB)             // W tile: 18432 B
#define STB (ATB + WTB)             // 55296 B per stage
static const int GEMM_SMEM = 3 * STB;   // 165888 B

// load fragments for one kc chunk: A 4x ldsm.x4 (64 rows), W 4x ldsm.x4 (64 cols)
#define G_LOAD_FRAGS(AF, WF, ABASE, WBASE, KC) do {                            \
    ldsm4(AF[0], (ABASE) + (mw * 64     ) * GPB + aoff + (KC) * 32);           \
    ldsm4(AF[1], (ABASE) + (mw * 64 + 16) * GPB + aoff + (KC) * 32);           \
    ldsm4(AF[2], (ABASE) + (mw * 64 + 32) * GPB + aoff + (KC) * 32);           \
    ldsm4(AF[3], (ABASE) + (mw * 64 + 48) * GPB + aoff + (KC) * 32);           \
    ldsm4(WF[0], (WBASE) + (nw * 64     ) * GPB + boff + (KC) * 32);           \
    ldsm4(WF[1], (WBASE) + (nw * 64 + 16) * GPB + boff + (KC) * 32);           \
    ldsm4(WF[2], (WBASE) + (nw * 64 + 32) * GPB + boff + (KC) * 32);           \
    ldsm4(WF[3], (WBASE) + (nw * 64 + 48) * GPB + boff + (KC) * 32);           \
} while (0)

#define G_MMA_ALL(AF, WF) do {                                                 \
    _Pragma("unroll")                                                          \
    for (int mt = 0; mt < 4; mt++) {                                           \
        _Pragma("unroll")                                                      \
        for (int p = 0; p < 4; p++) {                                          \
            mma16(acc[mt][2 * p    ], AF[mt], &WF[p][0]);                      \
            mma16(acc[mt][2 * p + 1], AF[mt], &WF[p][2]);                      \
        }                                                                      \
    }                                                                          \
} while (0)

template<int MODE>
__global__ void __launch_bounds__(256, 1)
gemm_h(const float* __restrict__ bias, float* __restrict__ C, int N, int K)
{
    extern __shared__ __align__(256) char smem[];
    const uint32_t sb = sa(smem);
    const int m0 = blockIdx.y * 256, n0 = blockIdx.x * 128;
    const int tid  = threadIdx.x;
    const int warp = tid >> 5, lane = tid & 31;
    const int mw = warp >> 1, nw = warp & 1;      // 4 x 2 warp grid, 64x64 per warp
    const int g  = lane >> 2, qq = lane & 3;

    const __half* Ag = (MODE == 1) ? g_ctx : g_x;       // [M][K]
    const __half* Wg = (MODE == 1) ? g_wout : g_wqkv;   // [N][K]

    float acc[4][8][4];
#pragma unroll
    for (int i = 0; i < 4; i++)
#pragma unroll
        for (int j = 0; j < 8; j++)
#pragma unroll
            for (int r = 0; r < 4; r++) acc[i][j][r] = 0.f;

    // A loader: 256 rows x 128B, 1 thread/row (8x cpa16)
    // W loader: 128 rows x 128B, 2 threads/row (4x cpa16)
    const int wrow = tid >> 1;
    const int wh   = (tid & 1) * 64;   // byte offset within W row
    auto load_tiles = [&](int kt, int s) {
        const __half* As = Ag + (size_t)(m0 + tid) * K + kt * 64;
        const __half* Ws = Wg + (size_t)(n0 + wrow) * K + kt * 64 + (wh >> 1);
        uint32_t ab = sb + s * STB;
        uint32_t wb = ab + ATB;
        uint32_t aofs = tid * GPB;
        uint32_t wofs = wrow * GPB + wh;
#pragma unroll
        for (int j = 0; j < 8; j++)
            cpa16(ab + aofs + j * 16, As + j * 8);
#pragma unroll
        for (int j = 0; j < 4; j++)
            cpa16(wb + wofs + j * 16, Ws + j * 8);
        CP_COMMIT;
    };

    // per-lane ldmatrix byte offsets within a tile
    const uint32_t aoff = (uint32_t)((lane & 15) * GPB + (lane >> 4) * 16);
    const uint32_t boff = (uint32_t)(((lane & 7) + ((lane >> 4) << 3)) * GPB
                                     + ((lane >> 3) & 1) * 16);

    uint32_t af0[4][4], wf0[4][4], af1[4][4], wf1[4][4];

    const int NT = K >> 6;   // k-tiles of 64
    load_tiles(0, 0);
    load_tiles(1, 1);
    CP_WAIT1;
    __syncthreads();
    G_LOAD_FRAGS(af0, wf0, sb, sb + ATB, 0);

    for (int kt = 0; kt < NT; kt++) {
        const int s = kt % 3;
        const uint32_t cab = sb + s * STB;
        const uint32_t cwb = cab + ATB;

        G_LOAD_FRAGS(af1, wf1, cab, cwb, 1);
        if (kt + 2 < NT) load_tiles(kt + 2, (kt + 2) % 3);
        G_MMA_ALL(af0, wf0);

        G_LOAD_FRAGS(af0, wf0, cab, cwb, 2);
        G_MMA_ALL(af1, wf1);

        G_LOAD_FRAGS(af1, wf1, cab, cwb, 3);
        G_MMA_ALL(af0, wf0);

        if (kt + 1 < NT) {
            CP_WAIT1;
            __syncthreads();
            const uint32_t nab = sb + ((kt + 1) % 3) * STB;
            G_LOAD_FRAGS(af0, wf0, nab, nab + ATB, 0);
        }
        G_MMA_ALL(af1, wf1);
    }

    // epilogue
#pragma unroll
    for (int mt = 0; mt < 4; mt++) {
#pragma unroll
        for (int nt = 0; nt < 8; nt++) {
            int col = n0 + nw * 64 + nt * 8 + 2 * qq;
            float b0 = __ldg(bias + col), b1 = __ldg(bias + col + 1);
#pragma unroll
            for (int half = 0; half < 2; half++) {
                int row = m0 + mw * 64 + mt * 16 + g + half * 8;
                float v0 = acc[mt][nt][half * 2    ] + b0;
                float v1 = acc[mt][nt][half * 2 + 1] + b1;
                if (MODE == 0) {
                    int c = col >> 10;            // 0:q 1:k 2:v
                    int h = (col >> 6) & 15;
                    int d = col & 63;
                    int b = row >> 11;
                    int s = row & 2047;
                    if (c == 2) {
                        // V transposed: [B,H,Dh,S]
                        size_t vb = ((size_t)((b * NHEAD + h) * HEAD_DIM + d)) * SEQ + s;
                        g_v[vb]       = __float2half_rn(v0);
                        g_v[vb + SEQ] = __float2half_rn(v1);
                    } else {
                        size_t idx = ((size_t)((b * NHEAD + h) * SEQ + s)) * HEAD_DIM + d;
                        __half* dst = (c == 0) ? g_q : g_k;
                        __half2 hv = __floats2half2_rn(v0, v1);
                        *reinterpret_cast<__half2*>(dst + idx) = hv;
                    }
                } else {
                    *reinterpret_cast<float2*>(C + (size_t)row * N + col) =
                        make_float2(v0, v1);
                }
            }
        }
    }
}

// ---------------- flash attention (fp16 MMA, R10 form) ----------------------
// grid: (S/128, H, B); block 256 (8 warps, 16 query rows each).
#define QTB (128 * GPB)             // 18432 B
#define KTB (64 * GPB)              // 9216 B
#define SK_OFF(s) (QTB + (s) * KTB)
#define SV_OFF(s) (QTB + 3 * KTB + (s) * KTB)
static const int ATTN_SMEM = QTB + 6 * KTB;   // 73728 B

#define A_LOADB(BF, BASE, KC) do {                                             \
    ldsm4(BF[0], (BASE) + ( 0) * GPB + boff + (KC) * 32);                      \
    ldsm4(BF[1], (BASE) + (16) * GPB + boff + (KC) * 32);                      \
    ldsm4(BF[2], (BASE) + (32) * GPB + boff + (KC) * 32);                      \
    ldsm4(BF[3], (BASE) + (48) * GPB + boff + (KC) * 32);                      \
} while (0)

#define A_MMA_S(QF, KF) do {                                                   \
    _Pragma("unroll")                                                          \
    for (int p = 0; p < 4; p++) {                                              \
        mma16(sacc[2 * p    ], QF, &KF[p][0]);                                 \
        mma16(sacc[2 * p + 1], QF, &KF[p][2]);                                 \
    }                                                                          \
} while (0)

__global__ void __launch_bounds__(256, 2)
attn_h()
{
    extern __shared__ __align__(256) char smem[];
    const uint32_t sb = sa(smem);

    const int tid = threadIdx.x, warp = tid >> 5, lane = tid & 31;

    const int qt = blockIdx.x, h = blockIdx.y, b = blockIdx.z;
    const size_t head_off = ((size_t)(b * NHEAD + h)) * SEQ * HEAD_DIM;
    const __half* Qg = g_q + head_off;
    const __half* Kg = g_k + head_off;
    const __half* Vg = g_v + head_off;   // [Dh][S]

    // K/V loaders: 64 rows x 128B, 4 threads/row
    const int kvrow = tid >> 2;
    const int kvq = (tid & 3) * 16;      // halves offset
    auto load_kv = [&](int kt, int s) {
        const __half* Ks = Kg + (size_t)(kt * 64 + kvrow) * HEAD_DIM + kvq;
        const __half* Vs = Vg + (size_t)kvrow * SEQ + kt * 64 + kvq;
        uint32_t kb = sb + SK_OFF(s) + kvrow * GPB + kvq * 2;
        uint32_t vb = sb + SV_OFF(s) + kvrow * GPB + kvq * 2;
#pragma unroll
        for (int j = 0; j < 2; j++) {
            cpa16(kb + j * 16, Ks + j * 8);
            cpa16(vb + j * 16, Vs + j * 8);
        }
        CP_COMMIT;
    };

    // Q: 128 rows x 128B, 2 threads/row (committed with kv tile 0)
    {
        const int qrow = tid >> 1;
        const int qh = (tid & 1) * 32;
        const __half* Qs = Qg + (size_t)(qt * 128 + qrow) * HEAD_DIM + qh;
        uint32_t qb = sb + qrow * GPB + qh * 2;
#pragma unroll
        for (int j = 0; j < 4; j++)
            cpa16(qb + j * 16, Qs + j * 8);
    }
    load_kv(0, 0);
    load_kv(1, 1);

    // ldmatrix per-lane offsets
    const uint32_t aoff = (uint32_t)((lane & 15) * GPB + (lane >> 4) * 16);
    const uint32_t boff = (uint32_t)(((lane & 7) + ((lane >> 4) << 3)) * GPB
                                     + ((lane >> 3) & 1) * 16);

    float oacc[8][4];
#pragma unroll
    for (int i = 0; i < 8; i++)
#pragma unroll
        for (int r = 0; r < 4; r++) oacc[i][r] = 0.f;
    float mrow[2] = {-1e30f, -1e30f};
    float lrow[2] = {0.f, 0.f};

    const float SCALE = 0.125f * 1.4426950408889634f;   // 1/sqrt(Dh) * log2(e)

    uint32_t qf[4][4];   // hoisted Q fragments (k-tile invariant)
    uint32_t kf0[4][4], kf1[4][4];

    const int NT = SEQ / 64;
    for (int kt = 0; kt < NT; kt++) {
        CP_WAIT1;
        __syncthreads();

        if (kt == 0) {
#pragma unroll
            for (int kc = 0; kc < 4; kc++)
                ldsm4(qf[kc], sb + (warp * 16) * GPB + aoff + kc * 32);
        }

        const int s = kt % 3;
        const uint32_t kb = sb + SK_OFF(s);
        const uint32_t vb = sb + SV_OFF(s);

        // S = Q K^T (16 x 64 per warp), K fragments double-buffered
        float sacc[8][4];
#pragma unroll
        for (int i = 0; i < 8; i++)
#pragma unroll
            for (int r = 0; r < 4; r++) sacc[i][r] = 0.f;

        A_LOADB(kf0, kb, 0);
        A_LOADB(kf1, kb, 1);
        A_MMA_S(qf[0], kf0);
        A_LOADB(kf0, kb, 2);
        A_MMA_S(qf[1], kf1);
        A_LOADB(kf1, kb, 3);
        A_MMA_S(qf[2], kf0);
        A_MMA_S(qf[3], kf1);

        // gmem prefetch moved off the post-barrier burst
        if (kt + 2 < NT) load_kv(kt + 2, (kt + 2) % 3);

#pragma unroll
        for (int nt = 0; nt < 8; nt++)
#pragma unroll
            for (int r = 0; r < 4; r++) sacc[nt][r] *= SCALE;

        // online softmax in log2 domain (two rows per thread: g and g+8)
#pragma unroll
        for (int rr = 0; rr < 2; rr++) {
            float mloc = -1e30f;
#pragma unroll
            for (int nt = 0; nt < 8; nt++)
                mloc = fmaxf(mloc, fmaxf(sacc[nt][rr * 2], sacc[nt][rr * 2 + 1]));
            mloc = fmaxf(mloc, __shfl_xor_sync(0xffffffffu, mloc, 1));
            mloc = fmaxf(mloc, __shfl_xor_sync(0xffffffffu, mloc, 2));
            float mnew  = fmaxf(mrow[rr], mloc);
            float alpha = ex2(mrow[rr] - mnew);
            mrow[rr] = mnew;
            float lsum = 0.f;
#pragma unroll
            for (int nt = 0; nt < 8; nt++) {
                float p0 = ex2(sacc[nt][rr * 2]     - mnew);
                float p1 = ex2(sacc[nt][rr * 2 + 1] - mnew);
                sacc[nt][rr * 2] = p0; sacc[nt][rr * 2 + 1] = p1;
                lsum += p0 + p1;
            }
            lsum += __shfl_xor_sync(0xffffffffu, lsum, 1);
            lsum += __shfl_xor_sync(0xffffffffu, lsum, 2);
            lrow[rr] = lrow[rr] * alpha + lsum;
#pragma unroll
            for (int dt = 0; dt < 8; dt++) {
                oacc[dt][rr * 2]     *= alpha;
                oacc[dt][rr * 2 + 1] *= alpha;
            }
        }

        // O += P @ V — ldsm first (latency covered by the cvt pack), then MMA
#pragma unroll
        for (int jc = 0; jc < 4; jc++) {
            uint32_t vf[4][4];
            A_LOADB(vf, vb, jc);
            uint32_t af[4];
            af[0] = h2u(sacc[2 * jc    ][0], sacc[2 * jc    ][1]);
            af[1] = h2u(sacc[2 * jc    ][2], sacc[2 * jc    ][3]);
            af[2] = h2u(sacc[2 * jc + 1][0], sacc[2 * jc + 1][1]);
            af[3] = h2u(sacc[2 * jc + 1][2], sacc[2 * jc + 1][3]);
#pragma unroll
            for (int p = 0; p < 4; p++) {
                mma16(oacc[2 * p    ], af, &vf[p][0]);
                mma16(oacc[2 * p + 1], af, &vf[p][2]);
            }
        }
    }

    // normalize; write ctx fp16 in [B,S,D] layout
    const int g = lane >> 2, qq = lane & 3;
#pragma unroll
    for (int rr = 0; rr < 2; rr++) {
        float inv = 1.f / lrow[rr];
        int s = qt * 128 + warp * 16 + g + rr * 8;
        size_t base = ((size_t)(b * SEQ + s)) * D_MODEL;
#pragma unroll
        for (int dt = 0; dt < 8; dt++) {
            int d0 = h * HEAD_DIM + dt * 8 + 2 * qq;
            __half2 hv = __floats2half2_rn(oacc[dt][rr * 2] * inv,
                                           oacc[dt][rr * 2 + 1] * inv);
            *reinterpret_cast<__half2*>(g_ctx + base + d0) = hv;
        }
    }
}

// ---------------- launch -----------------------------------------------------
extern "C" void kernel_launch(void* const* d_in, const int* in_sizes, int n_in,
                              void* d_out, int out_size)
{
    const float* x     = (const float*)d_in[0];
    const float* W_qkv = (const float*)d_in[1];
    const float* b_qkv = (const float*)d_in[2];
    const float* W_out = (const float*)d_in[3];
    const float* b_out = (const float*)d_in[4];
    float* out = (float*)d_out;

    cudaFuncSetAttribute(gemm_h<0>, cudaFuncAttributeMaxDynamicSharedMemorySize, GEMM_SMEM);
    cudaFuncSetAttribute(gemm_h<1>, cudaFuncAttributeMaxDynamicSharedMemorySize, GEMM_SMEM);
    cudaFuncSetAttribute(attn_h,    cudaFuncAttributeMaxDynamicSharedMemorySize, ATTN_SMEM);

    __half* gx; __half* gwq; __half* gwo;
    cudaGetSymbolAddress((void**)&gx,  g_x);
    cudaGetSymbolAddress((void**)&gwq, g_wqkv);
    cudaGetSymbolAddress((void**)&gwo, g_wout);

    // 0) prep: round x to fp16; transpose+round weights to [N][K] fp16
    round_h<<<2048, 256>>>(x, gx, MTOK * D_MODEL / 4);
    transpose_h<<<dim3(3 * D_MODEL / 32, D_MODEL / 32), dim3(32, 8)>>>(
        W_qkv, gwq, D_MODEL, 3 * D_MODEL);
    transpose_h<<<dim3(D_MODEL / 32, D_MODEL / 32), dim3(32, 8)>>>(
        W_out, gwo, D_MODEL, D_MODEL);

    // 1) QKV projection -> g_q/g_k ([B,H,S,Dh]), g_v ([B,H,Dh,S])
    gemm_h<0><<<dim3(3 * D_MODEL / 128, MTOK / 256), 256, GEMM_SMEM>>>(
        b_qkv, nullptr, 3 * D_MODEL, D_MODEL);

    // 2) flash attention -> ctx [B,S,D] fp16
    attn_h<<<dim3(SEQ / 128, NHEAD, BATCH), 256, ATTN_SMEM>>>();

    // 3) output projection (final fp32)
    gemm_h<1><<<dim3(D_MODEL / 128, MTOK / 256), 256, GEMM_SMEM>>>(
        b_out, out, D_MODEL, D_MODEL);
}

// round 14
// speedup vs baseline: 1.0029x; 1.0029x over previous
#include <cuda_runtime.h>
#include <cuda_fp16.h>
#include <cstdint>

#define D_MODEL 1024
#define NHEAD 16
#define HEAD_DIM 64
#define BATCH 4
#define SEQ 2048
#define MTOK (BATCH*SEQ)   // 8192
#define GRID_P 296         // 2 CTAs/SM x 148 SMs (persistent grid)

// ---------------- scratch (static device globals: allocation-free) ----------
__device__ __align__(256) __half g_q[(size_t)BATCH*NHEAD*SEQ*HEAD_DIM];   // [B,H,S,Dh] pre-scaled
__device__ __align__(256) __half g_k[(size_t)BATCH*NHEAD*SEQ*HEAD_DIM];   // [B,H,S,Dh]
__device__ __align__(256) __half g_v[(size_t)BATCH*NHEAD*SEQ*HEAD_DIM];   // [B,H,Dh,S] TRANSPOSED
__device__ __align__(256) __half g_ctx[(size_t)MTOK*D_MODEL];             // [B,S,D]
__device__ __align__(256) __half g_x[(size_t)MTOK*D_MODEL];               // [M][K]
__device__ __align__(256) __half g_wqkv[(size_t)3*D_MODEL*D_MODEL];       // [N][K] transposed
__device__ __align__(256) __half g_wout[(size_t)D_MODEL*D_MODEL];         // [N][K] transposed

// ---------------- helpers ---------------------------------------------------
__device__ __forceinline__ float ex2(float x) {
    float y;
    asm("ex2.approx.f32 %0, %1;" : "=f"(y) : "f"(x));
    return y;
}
__device__ __forceinline__ uint32_t sa(const void* p) {
    return (uint32_t)__cvta_generic_to_shared(p);
}
__device__ __forceinline__ void cpa16(uint32_t dst, const void* src) {
    asm volatile("cp.async.cg.shared.global [%0], [%1], 16;\n" :: "r"(dst), "l"(src));
}
#define CP_COMMIT asm volatile("cp.async.commit_group;\n" ::: "memory")
#define CP_WAIT1  asm volatile("cp.async.wait_group 1;\n" ::: "memory")
#define CP_WAIT0  asm volatile("cp.async.wait_group 0;\n" ::: "memory")

__device__ __forceinline__ uint32_t h2u(float a, float b) {
    __half2 h = __floats2half2_rn(a, b);
    return *reinterpret_cast<uint32_t*>(&h);
}
__device__ __forceinline__ void ldsm4(uint32_t* r, uint32_t addr) {
    asm volatile("ldmatrix.sync.aligned.m8n8.x4.shared.b16 {%0,%1,%2,%3}, [%4];"
                 : "=r"(r[0]), "=r"(r[1]), "=r"(r[2]), "=r"(r[3]) : "r"(addr));
}

// D(16x8,f32) += A(16x16 f16,row) * B(16x8 f16,col)
__device__ __forceinline__ void mma16(float* c, const uint32_t* a, const uint32_t* b) {
    asm volatile(
        "mma.sync.aligned.m16n8k16.row.col.f32.f16.f16.f32 "
        "{%0,%1,%2,%3}, {%4,%5,%6,%7}, {%8,%9}, {%0,%1,%2,%3};\n"
        : "+f"(c[0]), "+f"(c[1]), "+f"(c[2]), "+f"(c[3])
        : "r"(a[0]), "r"(a[1]), "r"(a[2]), "r"(a[3]), "r"(b[0]), "r"(b[1]));
}

// ---------------- prep kernels ----------------------------------------------
__global__ void round_h(const float* __restrict__ src, __half* __restrict__ dst, int n4)
{
    int stride = gridDim.x * blockDim.x;
    for (int i = blockIdx.x * blockDim.x + threadIdx.x; i < n4; i += stride) {
        float4 v = reinterpret_cast<const float4*>(src)[i];
        uint2 o = make_uint2(h2u(v.x, v.y), h2u(v.z, v.w));
        reinterpret_cast<uint2*>(dst)[i] = o;
    }
}

// W[K][N] fp32 -> Wt[N][K] fp16. grid (N/32, K/32), block (32,8).
__global__ void transpose_h(const float* __restrict__ src, __half* __restrict__ dst,
                            int Kdim, int Ndim)
{
    __shared__ __half ts[32][33];
    int n0 = blockIdx.x * 32, k0 = blockIdx.y * 32;
    int tx = threadIdx.x, ty = threadIdx.y;
#pragma unroll
    for (int r = 0; r < 4; r++)
        ts[ty + 8 * r][tx] = __float2half_rn(src[(size_t)(k0 + ty + 8 * r) * Ndim + n0 + tx]);
    __syncthreads();
#pragma unroll
    for (int r = 0; r < 4; r++)
        dst[(size_t)(n0 + ty + 8 * r) * Kdim + k0 + tx] = ts[tx][ty + 8 * r];
}

// ---------------- GEMM: persistent, 128x128 tile, fp16 MMA ------------------
#define GPB 144                     // smem pitch bytes (72 halves)
#define GTB (128 * GPB)             // 18432 B per operand tile
static const int GEMM_SMEM = 6 * GTB;   // 110592 B (3 stages x (A,W))

#define G_LOAD_FRAGS(AF, BF, ABASE, WBASE, KC) do {                            \
    ldsm4(AF[0], (ABASE) + (mw * 32     ) * GPB + aoff + (KC) * 32);           \
    ldsm4(AF[1], (ABASE) + (mw * 32 + 16) * GPB + aoff + (KC) * 32);           \
    ldsm4(BF[0], (WBASE) + (nw * 64     ) * GPB + boff + (KC) * 32);           \
    ldsm4(BF[1], (WBASE) + (nw * 64 + 16) * GPB + boff + (KC) * 32);           \
    ldsm4(BF[2], (WBASE) + (nw * 64 + 32) * GPB + boff + (KC) * 32);           \
    ldsm4(BF[3], (WBASE) + (nw * 64 + 48) * GPB + boff + (KC) * 32);           \
} while (0)

#define G_MMA_ALL(AF, BF) do {                                                 \
    _Pragma("unroll")                                                          \
    for (int mt = 0; mt < 2; mt++) {                                           \
        _Pragma("unroll")                                                      \
        for (int p = 0; p < 4; p++) {                                          \
            mma16(acc[mt][2 * p    ], AF[mt], &BF[p][0]);                      \
            mma16(acc[mt][2 * p + 1], AF[mt], &BF[p][2]);                      \
        }                                                                      \
    }                                                                          \
} while (0)

#define QSCALE 0.18033688011112042f   // 0.125 * log2(e)

template<int MODE>
__global__ void __launch_bounds__(256, 2)
gemm_h(const float* __restrict__ bias, float* __restrict__ C, int N, int K, int TN)
{
    extern __shared__ __align__(256) char smem[];
    const uint32_t sb = sa(smem);
    const int tid  = threadIdx.x;
    const int warp = tid >> 5, lane = tid & 31;
    const int mw = warp >> 1, nw = warp & 1;      // 4 x 2 warp grid, 32x64 per warp
    const int g  = lane >> 2, qq = lane & 3;

    const __half* Ag = (MODE == 1) ? g_ctx : g_x;       // [M][K]
    const __half* Wg = (MODE == 1) ? g_wout : g_wqkv;   // [N][K]

    const int lrow = tid >> 1;             // 128 rows, 2 threads/row
    const int lh   = (tid & 1) * 32;       // halves offset within row
    auto load_tiles = [&](int m0, int n0, int kt, int s) {
        const __half* As = Ag + (size_t)(m0 + lrow) * K + kt * 64 + lh;
        const __half* Ws = Wg + (size_t)(n0 + lrow) * K + kt * 64 + lh;
        uint32_t ab = sb + s * 2 * GTB;
        uint32_t wb = ab + GTB;
        uint32_t off = lrow * GPB + lh * 2;
#pragma unroll
        for (int j = 0; j < 4; j++) {
            cpa16(ab + off + j * 16, As + j * 8);
            cpa16(wb + off + j * 16, Ws + j * 8);
        }
        CP_COMMIT;
    };

    // per-lane ldmatrix byte offsets within a tile
    const uint32_t aoff = (uint32_t)((lane & 15) * GPB + (lane >> 4) * 16);
    const uint32_t boff = (uint32_t)(((lane & 7) + ((lane >> 4) << 3)) * GPB
                                     + ((lane >> 3) & 1) * 16);

    const int nb = N >> 7;
    const int NT = K >> 6;   // k-tiles of 64
    uint32_t af0[2][4], bf0[4][4], af1[2][4], bf1[4][4];
    float acc[2][8][4];

    for (int t = blockIdx.x; t < TN; t += gridDim.x) {
        const int m0 = (t / nb) << 7;
        const int n0 = (t % nb) << 7;

        __syncthreads();   // all warps done with previous tile's smem
#pragma unroll
        for (int i = 0; i < 2; i++)
#pragma unroll
            for (int j = 0; j < 8; j++)
#pragma unroll
                for (int r = 0; r < 4; r++) acc[i][j][r] = 0.f;

        load_tiles(m0, n0, 0, 0);
        load_tiles(m0, n0, 1, 1);
        CP_WAIT1;
        __syncthreads();
        G_LOAD_FRAGS(af0, bf0, sb, sb + GTB, 0);

        for (int kt = 0; kt < NT; kt++) {
            const int s = kt % 3;
            const uint32_t cab = sb + s * 2 * GTB;
            const uint32_t cwb = cab + GTB;

            G_LOAD_FRAGS(af1, bf1, cab, cwb, 1);
            if (kt + 2 < NT) load_tiles(m0, n0, kt + 2, (kt + 2) % 3);
            G_MMA_ALL(af0, bf0);

            G_LOAD_FRAGS(af0, bf0, cab, cwb, 2);
            G_MMA_ALL(af1, bf1);

            G_LOAD_FRAGS(af1, bf1, cab, cwb, 3);
            G_MMA_ALL(af0, bf0);

            if (kt + 1 < NT) {
                if (kt + 2 < NT) { CP_WAIT1; } else { CP_WAIT0; }  // drain fully for last tile
                __syncthreads();
                const uint32_t nab = sb + ((kt + 1) % 3) * 2 * GTB;
                G_LOAD_FRAGS(af0, bf0, nab, nab + GTB, 0);
            }
            G_MMA_ALL(af1, bf1);
        }

        // epilogue
#pragma unroll
        for (int mt = 0; mt < 2; mt++) {
#pragma unroll
            for (int nt = 0; nt < 8; nt++) {
                int col = n0 + nw * 64 + nt * 8 + 2 * qq;
                float b0 = __ldg(bias + col), b1 = __ldg(bias + col + 1);
#pragma unroll
                for (int half = 0; half < 2; half++) {
                    int row = m0 + mw * 32 + mt * 16 + g + half * 8;
                    float v0 = acc[mt][nt][half * 2    ] + b0;
                    float v1 = acc[mt][nt][half * 2 + 1] + b1;
                    if (MODE == 0) {
                        int c = col >> 10;            // 0:q 1:k 2:v
                        int h = (col >> 6) & 15;
                        int d = col & 63;
                        int b = row >> 11;
                        int s = row & 2047;
                        if (c == 2) {
                            // V transposed: [B,H,Dh,S]
                            size_t vb = ((size_t)((b * NHEAD + h) * HEAD_DIM + d)) * SEQ + s;
                            g_v[vb]       = __float2half_rn(v0);
                            g_v[vb + SEQ] = __float2half_rn(v1);
                        } else {
                            if (c == 0) { v0 *= QSCALE; v1 *= QSCALE; }  // fold softmax scale into Q
                            size_t idx = ((size_t)((b * NHEAD + h) * SEQ + s)) * HEAD_DIM + d;
                            __half* dst = (c == 0) ? g_q : g_k;
                            __half2 hv = __floats2half2_rn(v0, v1);
                            *reinterpret_cast<__half2*>(dst + idx) = hv;
                        }
                    } else {
                        *reinterpret_cast<float2*>(C + (size_t)row * N + col) =
                            make_float2(v0, v1);
                    }
                }
            }
        }
    }
}

// ---------------- flash attention (persistent, fp16 MMA) --------------------
#define QTB (128 * GPB)             // 18432 B
#define KTB (64 * GPB)              // 9216 B
#define SK_OFF(s) (QTB + (s) * KTB)
#define SV_OFF(s) (QTB + 3 * KTB + (s) * KTB)
static const int ATTN_SMEM = QTB + 6 * KTB;   // 73728 B

#define A_LOADB(BF, BASE, KC) do {                                             \
    ldsm4(BF[0], (BASE) + ( 0) * GPB + boff + (KC) * 32);                      \
    ldsm4(BF[1], (BASE) + (16) * GPB + boff + (KC) * 32);                      \
    ldsm4(BF[2], (BASE) + (32) * GPB + boff + (KC) * 32);                      \
    ldsm4(BF[3], (BASE) + (48) * GPB + boff + (KC) * 32);                      \
} while (0)

#define A_MMA_S(QF, KF) do {                                                   \
    _Pragma("unroll")                                                          \
    for (int p = 0; p < 4; p++) {                                              \
        mma16(sacc[2 * p    ], QF, &KF[p][0]);                                 \
        mma16(sacc[2 * p + 1], QF, &KF[p][2]);                                 \
    }                                                                          \
} while (0)

__global__ void __launch_bounds__(256, 2)
attn_h()
{
    extern __shared__ __align__(256) char smem[];
    const uint32_t sb = sa(smem);

    const int tid = threadIdx.x, warp = tid >> 5, lane = tid & 31;
    const int g = lane >> 2, qq = lane & 3;

    // ldmatrix per-lane offsets
    const uint32_t aoff = (uint32_t)((lane & 15) * GPB + (lane >> 4) * 16);
    const uint32_t boff = (uint32_t)(((lane & 7) + ((lane >> 4) << 3)) * GPB
                                     + ((lane >> 3) & 1) * 16);

    const int kvrow = tid >> 2;
    const int kvq = (tid & 3) * 16;      // halves offset
    const int NT = SEQ / 64;             // 32
    const int TN = (SEQ / 128) * NHEAD * BATCH;   // 1024

    for (int t = blockIdx.x; t < TN; t += gridDim.x) {
        const int qt = t & 15, h = (t >> 4) & 15, b = t >> 8;
        const size_t head_off = ((size_t)(b * NHEAD + h)) * SEQ * HEAD_DIM;
        const __half* Qg = g_q + head_off;
        const __half* Kg = g_k + head_off;
        const __half* Vg = g_v + head_off;   // [Dh][S]

        auto load_kv = [&](int kt, int s) {
            const __half* Ks = Kg + (size_t)(kt * 64 + kvrow) * HEAD_DIM + kvq;
            const __half* Vs = Vg + (size_t)kvrow * SEQ + kt * 64 + kvq;
            uint32_t kb = sb + SK_OFF(s) + kvrow * GPB + kvq * 2;
            uint32_t vb = sb + SV_OFF(s) + kvrow * GPB + kvq * 2;
#pragma unroll
            for (int j = 0; j < 2; j++) {
                cpa16(kb + j * 16, Ks + j * 8);
                cpa16(vb + j * 16, Vs + j * 8);
            }
            CP_COMMIT;
        };

        __syncthreads();   // all warps done with previous tile's smem

        // Q: 128 rows x 128B, 2 threads/row (committed with kv tile 0)
        {
            const int qrow = tid >> 1;
            const int qh = (tid & 1) * 32;
            const __half* Qs = Qg + (size_t)(qt * 128 + qrow) * HEAD_DIM + qh;
            uint32_t qb = sb + qrow * GPB + qh * 2;
#pragma unroll
            for (int j = 0; j < 4; j++)
                cpa16(qb + j * 16, Qs + j * 8);
        }
        load_kv(0, 0);
        load_kv(1, 1);

        float oacc[8][4];
#pragma unroll
        for (int i = 0; i < 8; i++)
#pragma unroll
            for (int r = 0; r < 4; r++) oacc[i][r] = 0.f;
        float mrow[2] = {-1e30f, -1e30f};
        float lrow[2] = {0.f, 0.f};

        uint32_t qf[4][4];   // hoisted Q fragments (k-tile invariant)
        uint32_t kf0[4][4], kf1[4][4];

        for (int kt = 0; kt < NT; kt++) {
            if (kt + 1 < NT) { CP_WAIT1; } else { CP_WAIT0; }   // drain fully for last tile
            __syncthreads();

            if (kt == 0) {
#pragma unroll
                for (int kc = 0; kc < 4; kc++)
                    ldsm4(qf[kc], sb + (warp * 16) * GPB + aoff + kc * 32);
            }

            const int s = kt % 3;
            const uint32_t kb = sb + SK_OFF(s);
            const uint32_t vb = sb + SV_OFF(s);

            // S = Q K^T (16 x 64 per warp); Q pre-scaled by 0.125*log2(e)
            float sacc[8][4];
#pragma unroll
            for (int i = 0; i < 8; i++)
#pragma unroll
                for (int r = 0; r < 4; r++) sacc[i][r] = 0.f;

            A_LOADB(kf0, kb, 0);
            A_LOADB(kf1, kb, 1);
            A_MMA_S(qf[0], kf0);
            A_LOADB(kf0, kb, 2);
            A_MMA_S(qf[1], kf1);
            A_LOADB(kf1, kb, 3);
            A_MMA_S(qf[2], kf0);
            A_MMA_S(qf[3], kf1);

            // gmem prefetch moved off the post-barrier burst
            if (kt + 2 < NT) load_kv(kt + 2, (kt + 2) % 3);

            // online softmax in log2 domain (scores already scaled)
#pragma unroll
            for (int rr = 0; rr < 2; rr++) {
                float mloc = -1e30f;
#pragma unroll
                for (int nt = 0; nt < 8; nt++)
                    mloc = fmaxf(mloc, fmaxf(sacc[nt][rr * 2], sacc[nt][rr * 2 + 1]));
                mloc = fmaxf(mloc, __shfl_xor_sync(0xffffffffu, mloc, 1));
                mloc = fmaxf(mloc, __shfl_xor_sync(0xffffffffu, mloc, 2));
                float mnew  = fmaxf(mrow[rr], mloc);
                float alpha = ex2(mrow[rr] - mnew);
                mrow[rr] = mnew;
                float lsum = 0.f;
#pragma unroll
                for (int nt = 0; nt < 8; nt++) {
                    float p0 = ex2(sacc[nt][rr * 2]     - mnew);
                    float p1 = ex2(sacc[nt][rr * 2 + 1] - mnew);
                    sacc[nt][rr * 2] = p0; sacc[nt][rr * 2 + 1] = p1;
                    lsum += p0 + p1;
                }
                lsum += __shfl_xor_sync(0xffffffffu, lsum, 1);
                lsum += __shfl_xor_sync(0xffffffffu, lsum, 2);
                lrow[rr] = lrow[rr] * alpha + lsum;
#pragma unroll
                for (int dt = 0; dt < 8; dt++) {
                    oacc[dt][rr * 2]     *= alpha;
                    oacc[dt][rr * 2 + 1] *= alpha;
                }
            }

            // O += P @ V — ldsm first (latency covered by the cvt pack), then MMA
#pragma unroll
            for (int jc = 0; jc < 4; jc++) {
                uint32_t vf[4][4];
                A_LOADB(vf, vb, jc);
                uint32_t af[4];
                af[0] = h2u(sacc[2 * jc    ][0], sacc[2 * jc    ][1]);
                af[1] = h2u(sacc[2 * jc    ][2], sacc[2 * jc    ][3]);
                af[2] = h2u(sacc[2 * jc + 1][0], sacc[2 * jc + 1][1]);
                af[3] = h2u(sacc[2 * jc + 1][2], sacc[2 * jc + 1][3]);
#pragma unroll
                for (int p = 0; p < 4; p++) {
                    mma16(oacc[2 * p    ], af, &vf[p][0]);
                    mma16(oacc[2 * p + 1], af, &vf[p][2]);
                }
            }
        }

        // normalize; write ctx fp16 in [B,S,D] layout
#pragma unroll
        for (int rr = 0; rr < 2; rr++) {
            float inv = 1.f / lrow[rr];
            int s = qt * 128 + warp * 16 + g + rr * 8;
            size_t base = ((size_t)(b * SEQ + s)) * D_MODEL;
#pragma unroll
            for (int dt = 0; dt < 8; dt++) {
                int d0 = h * HEAD_DIM + dt * 8 + 2 * qq;
                __half2 hv = __floats2half2_rn(oacc[dt][rr * 2] * inv,
                                               oacc[dt][rr * 2 + 1] * inv);
                *reinterpret_cast<__half2*>(g_ctx + base + d0) = hv;
            }
        }
    }
}

// ---------------- launch -----------------------------------------------------
extern "C" void kernel_launch(void* const* d_in, const int* in_sizes, int n_in,
                              void* d_out, int out_size)
{
    const float* x     = (const float*)d_in[0];
    const float* W_qkv = (const float*)d_in[1];
    const float* b_qkv = (const float*)d_in[2];
    const float* W_out = (const float*)d_in[3];
    const float* b_out = (const float*)d_in[4];
    float* out = (float*)d_out;

    cudaFuncSetAttribute(gemm_h<0>, cudaFuncAttributeMaxDynamicSharedMemorySize, GEMM_SMEM);
    cudaFuncSetAttribute(gemm_h<1>, cudaFuncAttributeMaxDynamicSharedMemorySize, GEMM_SMEM);
    cudaFuncSetAttribute(attn_h,    cudaFuncAttributeMaxDynamicSharedMemorySize, ATTN_SMEM);

    __half* gx; __half* gwq; __half* gwo;
    cudaGetSymbolAddress((void**)&gx,  g_x);
    cudaGetSymbolAddress((void**)&gwq, g_wqkv);
    cudaGetSymbolAddress((void**)&gwo, g_wout);

    // 0) prep: round x to fp16; transpose+round weights to [N][K] fp16
    round_h<<<2048, 256>>>(x, gx, MTOK * D_MODEL / 4);
    transpose_h<<<dim3(3 * D_MODEL / 32, D_MODEL / 32), dim3(32, 8)>>>(
        W_qkv, gwq, D_MODEL, 3 * D_MODEL);
    transpose_h<<<dim3(D_MODEL / 32, D_MODEL / 32), dim3(32, 8)>>>(
        W_out, gwo, D_MODEL, D_MODEL);

    // 1) QKV projection -> g_q (pre-scaled) / g_k ([B,H,S,Dh]), g_v ([B,H,Dh,S])
    gemm_h<0><<<GRID_P, 256, GEMM_SMEM>>>(
        b_qkv, nullptr, 3 * D_MODEL, D_MODEL, (3 * D_MODEL / 128) * (MTOK / 128));

    // 2) flash attention -> ctx [B,S,D] fp16
    attn_h<<<GRID_P, 256, ATTN_SMEM>>>();

    // 3) output projection (final fp32)
    gemm_h<1><<<GRID_P, 256, GEMM_SMEM>>>(
        b_out, out, D_MODEL, D_MODEL, (D_MODEL / 128) * (MTOK / 128));
}

// round 15
// speedup vs baseline: 1.0582x; 1.0551x over previous
#include <cuda_runtime.h>
#include <cuda_fp16.h>
#include <cstdint>

#define D_MODEL 1024
#define NHEAD 16
#define HEAD_DIM 64
#define BATCH 4
#define SEQ 2048
#define MTOK (BATCH*SEQ)   // 8192

// ---------------- scratch (static device globals: allocation-free) ----------
__device__ __align__(256) __half g_q[(size_t)BATCH*NHEAD*SEQ*HEAD_DIM];   // [B,H,S,Dh] pre-scaled
__device__ __align__(256) __half g_k[(size_t)BATCH*NHEAD*SEQ*HEAD_DIM];   // [B,H,S,Dh]
__device__ __align__(256) __half g_v[(size_t)BATCH*NHEAD*SEQ*HEAD_DIM];   // [B,H,S,Dh]
__device__ __align__(256) __half g_ctx[(size_t)MTOK*D_MODEL];             // [B,S,D]
__device__ __align__(256) __half g_x[(size_t)MTOK*D_MODEL];               // [M][K]
__device__ __align__(256) __half g_wqkv[(size_t)3*D_MODEL*D_MODEL];       // [N][K] transposed
__device__ __align__(256) __half g_wout[(size_t)D_MODEL*D_MODEL];         // [N][K] transposed

// ---------------- helpers ---------------------------------------------------
__device__ __forceinline__ float ex2(float x) {
    float y;
    asm("ex2.approx.f32 %0, %1;" : "=f"(y) : "f"(x));
    return y;
}
__device__ __forceinline__ uint32_t sa(const void* p) {
    return (uint32_t)__cvta_generic_to_shared(p);
}
__device__ __forceinline__ void cpa16(uint32_t dst, const void* src) {
    asm volatile("cp.async.cg.shared.global [%0], [%1], 16;\n" :: "r"(dst), "l"(src));
}
#define CP_COMMIT asm volatile("cp.async.commit_group;\n" ::: "memory")
#define CP_WAIT1  asm volatile("cp.async.wait_group 1;\n" ::: "memory")
#define CP_WAIT0  asm volatile("cp.async.wait_group 0;\n" ::: "memory")

__device__ __forceinline__ uint32_t h2u(float a, float b) {
    __half2 h = __floats2half2_rn(a, b);
    return *reinterpret_cast<uint32_t*>(&h);
}
__device__ __forceinline__ void ldsm4(uint32_t* r, uint32_t addr) {
    asm volatile("ldmatrix.sync.aligned.m8n8.x4.shared.b16 {%0,%1,%2,%3}, [%4];"
                 : "=r"(r[0]), "=r"(r[1]), "=r"(r[2]), "=r"(r[3]) : "r"(addr));
}
__device__ __forceinline__ void ldsm4t(uint32_t* r, uint32_t addr) {
    asm volatile("ldmatrix.sync.aligned.m8n8.x4.trans.shared.b16 {%0,%1,%2,%3}, [%4];"
                 : "=r"(r[0]), "=r"(r[1]), "=r"(r[2]), "=r"(r[3]) : "r"(addr));
}

// D(16x8,f32) += A(16x16 f16,row) * B(16x8 f16,col)
__device__ __forceinline__ void mma16(float* c, const uint32_t* a, const uint32_t* b) {
    asm volatile(
        "mma.sync.aligned.m16n8k16.row.col.f32.f16.f16.f32 "
        "{%0,%1,%2,%3}, {%4,%5,%6,%7}, {%8,%9}, {%0,%1,%2,%3};\n"
        : "+f"(c[0]), "+f"(c[1]), "+f"(c[2]), "+f"(c[3])
        : "r"(a[0]), "r"(a[1]), "r"(a[2]), "r"(a[3]), "r"(b[0]), "r"(b[1]));
}

// ---------------- prep kernels ----------------------------------------------
__global__ void round_h(const float* __restrict__ src, __half* __restrict__ dst, int n4)
{
    int stride = gridDim.x * blockDim.x;
    for (int i = blockIdx.x * blockDim.x + threadIdx.x; i < n4; i += stride) {
        float4 v = reinterpret_cast<const float4*>(src)[i];
        uint2 o = make_uint2(h2u(v.x, v.y), h2u(v.z, v.w));
        reinterpret_cast<uint2*>(dst)[i] = o;
    }
}

// W[K][N] fp32 -> Wt[N][K] fp16. grid (N/32, K/32), block (32,8).
__global__ void transpose_h(const float* __restrict__ src, __half* __restrict__ dst,
                            int Kdim, int Ndim)
{
    __shared__ __half ts[32][33];
    int n0 = blockIdx.x * 32, k0 = blockIdx.y * 32;
    int tx = threadIdx.x, ty = threadIdx.y;
#pragma unroll
    for (int r = 0; r < 4; r++)
        ts[ty + 8 * r][tx] = __float2half_rn(src[(size_t)(k0 + ty + 8 * r) * Ndim + n0 + tx]);
    __syncthreads();
#pragma unroll
    for (int r = 0; r < 4; r++)
        dst[(size_t)(n0 + ty + 8 * r) * Kdim + k0 + tx] = ts[tx][ty + 8 * r];
}

// ---------------- GEMM: C[M,N] = A[M,K] @ Wt[N,K]^T + bias (fp16 MMA) -------
// 128x128 CTA tile, k-tile 64, 3-stage cp.async, register-double-buffered
// ldmatrix fragments (software pipeline: frag loads lead MMAs by one kc).
#define GPB 144                     // smem pitch bytes (72 halves)
#define GTB (128 * GPB)             // 18432 B per operand tile
static const int GEMM_SMEM = 6 * GTB;   // 110592 B (3 stages x (A,W))

#define G_LOAD_FRAGS(AF, BF, ABASE, WBASE, KC) do {                            \
    ldsm4(AF[0], (ABASE) + (mw * 32     ) * GPB + aoff + (KC) * 32);           \
    ldsm4(AF[1], (ABASE) + (mw * 32 + 16) * GPB + aoff + (KC) * 32);           \
    ldsm4(BF[0], (WBASE) + (nw * 64     ) * GPB + boff + (KC) * 32);           \
    ldsm4(BF[1], (WBASE) + (nw * 64 + 16) * GPB + boff + (KC) * 32);           \
    ldsm4(BF[2], (WBASE) + (nw * 64 + 32) * GPB + boff + (KC) * 32);           \
    ldsm4(BF[3], (WBASE) + (nw * 64 + 48) * GPB + boff + (KC) * 32);           \
} while (0)

#define G_MMA_ALL(AF, BF) do {                                                 \
    _Pragma("unroll")                                                          \
    for (int mt = 0; mt < 2; mt++) {                                           \
        _Pragma("unroll")                                                      \
        for (int p = 0; p < 4; p++) {                                          \
            mma16(acc[mt][2 * p    ], AF[mt], &BF[p][0]);                      \
            mma16(acc[mt][2 * p + 1], AF[mt], &BF[p][2]);                      \
        }                                                                      \
    }                                                                          \
} while (0)

#define QSCALE 0.18033688011112042f   // 0.125 * log2(e)

template<int MODE>
__global__ void __launch_bounds__(256, 2)
gemm_h(const float* __restrict__ bias, float* __restrict__ C, int N, int K)
{
    extern __shared__ __align__(256) char smem[];
    const uint32_t sb = sa(smem);
    const int m0 = blockIdx.y * 128, n0 = blockIdx.x * 128;
    const int tid  = threadIdx.x;
    const int warp = tid >> 5, lane = tid & 31;
    const int mw = warp >> 1, nw = warp & 1;      // 4 x 2 warp grid, 32x64 per warp
    const int g  = lane >> 2, qq = lane & 3;

    const __half* Ag = (MODE == 1) ? g_ctx : g_x;       // [M][K]
    const __half* Wg = (MODE == 1) ? g_wout : g_wqkv;   // [N][K]

    float acc[2][8][4];
#pragma unroll
    for (int i = 0; i < 2; i++)
#pragma unroll
        for (int j = 0; j < 8; j++)
#pragma unroll
            for (int r = 0; r < 4; r++) acc[i][j][r] = 0.f;

    const int lrow = tid >> 1;             // 128 rows, 2 threads/row
    const int lh   = (tid & 1) * 32;       // halves offset within row
    auto load_tiles = [&](int kt, int s) {
        const __half* As = Ag + (size_t)(m0 + lrow) * K + kt * 64 + lh;
        const __half* Ws = Wg + (size_t)(n0 + lrow) * K + kt * 64 + lh;
        uint32_t ab = sb + s * 2 * GTB;
        uint32_t wb = ab + GTB;
        uint32_t off = lrow * GPB + lh * 2;
#pragma unroll
        for (int j = 0; j < 4; j++) {
            cpa16(ab + off + j * 16, As + j * 8);
            cpa16(wb + off + j * 16, Ws + j * 8);
        }
        CP_COMMIT;
    };

    // per-lane ldmatrix byte offsets within a tile
    const uint32_t aoff = (uint32_t)((lane & 15) * GPB + (lane >> 4) * 16);
    const uint32_t boff = (uint32_t)(((lane & 7) + ((lane >> 4) << 3)) * GPB
                                     + ((lane >> 3) & 1) * 16);

    uint32_t af0[2][4], bf0[4][4], af1[2][4], bf1[4][4];

    const int NT = K >> 6;   // k-tiles of 64
    load_tiles(0, 0);
    load_tiles(1, 1);
    CP_WAIT1;
    __syncthreads();
    G_LOAD_FRAGS(af0, bf0, sb, sb + GTB, 0);

    for (int kt = 0; kt < NT; kt++) {
        const int s = kt % 3;
        const uint32_t cab = sb + s * 2 * GTB;
        const uint32_t cwb = cab + GTB;

        G_LOAD_FRAGS(af1, bf1, cab, cwb, 1);
        if (kt + 2 < NT) load_tiles(kt + 2, (kt + 2) % 3);
        G_MMA_ALL(af0, bf0);

        G_LOAD_FRAGS(af0, bf0, cab, cwb, 2);
        G_MMA_ALL(af1, bf1);

        G_LOAD_FRAGS(af1, bf1, cab, cwb, 3);
        G_MMA_ALL(af0, bf0);

        if (kt + 1 < NT) {
            if (kt + 2 < NT) { CP_WAIT1; } else { CP_WAIT0; }  // full drain before final tile
            __syncthreads();
            const uint32_t nab = sb + ((kt + 1) % 3) * 2 * GTB;
            G_LOAD_FRAGS(af0, bf0, nab, nab + GTB, 0);
        }
        G_MMA_ALL(af1, bf1);
    }

    // epilogue — Q/K/V all coalesced half2 stores ([B,H,S,Dh])
#pragma unroll
    for (int mt = 0; mt < 2; mt++) {
#pragma unroll
        for (int nt = 0; nt < 8; nt++) {
            int col = n0 + nw * 64 + nt * 8 + 2 * qq;
            float b0 = __ldg(bias + col), b1 = __ldg(bias + col + 1);
#pragma unroll
            for (int half = 0; half < 2; half++) {
                int row = m0 + mw * 32 + mt * 16 + g + half * 8;
                float v0 = acc[mt][nt][half * 2    ] + b0;
                float v1 = acc[mt][nt][half * 2 + 1] + b1;
                if (MODE == 0) {
                    int c = col >> 10;            // 0:q 1:k 2:v
                    int h = (col >> 6) & 15;
                    int d = col & 63;
                    int b = row >> 11;
                    int s = row & 2047;
                    if (c == 0) { v0 *= QSCALE; v1 *= QSCALE; }   // fold softmax scale into Q
                    size_t idx = ((size_t)((b * NHEAD + h) * SEQ + s)) * HEAD_DIM + d;
                    __half* dst = (c == 0) ? g_q : (c == 1) ? g_k : g_v;
                    __half2 hv = __floats2half2_rn(v0, v1);
                    *reinterpret_cast<__half2*>(dst + idx) = hv;
                } else {
                    *reinterpret_cast<float2*>(C + (size_t)row * N + col) =
                        make_float2(v0, v1);
                }
            }
        }
    }
}

// ---------------- flash attention (fp16 MMA, trans-ldsm PV) -----------------
// grid: (S/128, H, B); block 256 (8 warps, 16 query rows each).
#define QTB (128 * GPB)             // 18432 B
#define KTB (64 * GPB)              // 9216 B
#define SK_OFF(s) (QTB + (s) * KTB)
#define SV_OFF(s) (QTB + 3 * KTB + (s) * KTB)
static const int ATTN_SMEM = QTB + 6 * KTB;   // 73728 B

#define A_LOADB(BF, BASE, KC) do {                                             \
    ldsm4(BF[0], (BASE) + ( 0) * GPB + boff + (KC) * 32);                      \
    ldsm4(BF[1], (BASE) + (16) * GPB + boff + (KC) * 32);                      \
    ldsm4(BF[2], (BASE) + (32) * GPB + boff + (KC) * 32);                      \
    ldsm4(BF[3], (BASE) + (48) * GPB + boff + (KC) * 32);                      \
} while (0)

#define A_MMA_S(QF, KF) do {                                                   \
    _Pragma("unroll")                                                          \
    for (int p = 0; p < 4; p++) {                                              \
        mma16(sacc[2 * p    ], QF, &KF[p][0]);                                 \
        mma16(sacc[2 * p + 1], QF, &KF[p][2]);                                 \
    }                                                                          \
} while (0)

__global__ void __launch_bounds__(256, 2)
attn_h()
{
    extern __shared__ __align__(256) char smem[];
    const uint32_t sb = sa(smem);

    const int tid = threadIdx.x, warp = tid >> 5, lane = tid & 31;

    const int qt = blockIdx.x, h = blockIdx.y, b = blockIdx.z;
    const size_t head_off = ((size_t)(b * NHEAD + h)) * SEQ * HEAD_DIM;
    const __half* Qg = g_q + head_off;
    const __half* Kg = g_k + head_off;
    const __half* Vg = g_v + head_off;   // [S][Dh]

    // K/V loaders: 64 rows x 128B, 4 threads/row (identical layouts now)
    const int kvrow = tid >> 2;
    const int kvq = (tid & 3) * 16;      // halves offset
    auto load_kv = [&](int kt, int s) {
        const __half* Ks = Kg + (size_t)(kt * 64 + kvrow) * HEAD_DIM + kvq;
        const __half* Vs = Vg + (size_t)(kt * 64 + kvrow) * HEAD_DIM + kvq;
        uint32_t kb = sb + SK_OFF(s) + kvrow * GPB + kvq * 2;
        uint32_t vb = sb + SV_OFF(s) + kvrow * GPB + kvq * 2;
#pragma unroll
        for (int j = 0; j < 2; j++) {
            cpa16(kb + j * 16, Ks + j * 8);
            cpa16(vb + j * 16, Vs + j * 8);
        }
        CP_COMMIT;
    };

    // Q: 128 rows x 128B, 2 threads/row (committed with kv tile 0)
    {
        const int qrow = tid >> 1;
        const int qh = (tid & 1) * 32;
        const __half* Qs = Qg + (size_t)(qt * 128 + qrow) * HEAD_DIM + qh;
        uint32_t qb = sb + qrow * GPB + qh * 2;
#pragma unroll
        for (int j = 0; j < 4; j++)
            cpa16(qb + j * 16, Qs + j * 8);
    }
    load_kv(0, 0);
    load_kv(1, 1);

    // ldmatrix per-lane offsets
    const uint32_t aoff = (uint32_t)((lane & 15) * GPB + (lane >> 4) * 16);
    const uint32_t boff = (uint32_t)(((lane & 7) + ((lane >> 4) << 3)) * GPB
                                     + ((lane >> 3) & 1) * 16);
    // trans-ldsm offset for V (B-frags of V^T from [s][d] tiles)
    const uint32_t voff = (uint32_t)((lane & 15) * GPB + (lane >> 4) * 16);

    float oacc[8][4];
#pragma unroll
    for (int i = 0; i < 8; i++)
#pragma unroll
        for (int r = 0; r < 4; r++) oacc[i][r] = 0.f;
    float mrow[2] = {-1e30f, -1e30f};
    float lrow[2] = {0.f, 0.f};

    uint32_t qf[4][4];   // hoisted Q fragments (k-tile invariant; Q pre-scaled)
    uint32_t kf0[4][4], kf1[4][4];

    const int NT = SEQ / 64;
    for (int kt = 0; kt < NT; kt++) {
        if (kt + 1 < NT) { CP_WAIT1; } else { CP_WAIT0; }   // full drain on last tile
        __syncthreads();

        if (kt == 0) {
#pragma unroll
            for (int kc = 0; kc < 4; kc++)
                ldsm4(qf[kc], sb + (warp * 16) * GPB + aoff + kc * 32);
        }

        const int s = kt % 3;
        const uint32_t kb = sb + SK_OFF(s);
        const uint32_t vb = sb + SV_OFF(s);

        // S = Q K^T (16 x 64 per warp), K fragments double-buffered
        float sacc[8][4];
#pragma unroll
        for (int i = 0; i < 8; i++)
#pragma unroll
            for (int r = 0; r < 4; r++) sacc[i][r] = 0.f;

        A_LOADB(kf0, kb, 0);
        A_LOADB(kf1, kb, 1);
        A_MMA_S(qf[0], kf0);
        A_LOADB(kf0, kb, 2);
        A_MMA_S(qf[1], kf1);
        A_LOADB(kf1, kb, 3);
        A_MMA_S(qf[2], kf0);
        A_MMA_S(qf[3], kf1);

        // gmem prefetch moved off the post-barrier burst
        if (kt + 2 < NT) load_kv(kt + 2, (kt + 2) % 3);

        // online softmax in log2 domain (scores pre-scaled via Q)
#pragma unroll
        for (int rr = 0; rr < 2; rr++) {
            float mloc = -1e30f;
#pragma unroll
            for (int nt = 0; nt < 8; nt++)
                mloc = fmaxf(mloc, fmaxf(sacc[nt][rr * 2], sacc[nt][rr * 2 + 1]));
            mloc = fmaxf(mloc, __shfl_xor_sync(0xffffffffu, mloc, 1));
            mloc = fmaxf(mloc, __shfl_xor_sync(0xffffffffu, mloc, 2));
            float mnew  = fmaxf(mrow[rr], mloc);
            float alpha = ex2(mrow[rr] - mnew);
            mrow[rr] = mnew;
            float lsum = 0.f;
#pragma unroll
            for (int nt = 0; nt < 8; nt++) {
                float p0 = ex2(sacc[nt][rr * 2]     - mnew);
                float p1 = ex2(sacc[nt][rr * 2 + 1] - mnew);
                sacc[nt][rr * 2] = p0; sacc[nt][rr * 2 + 1] = p1;
                lsum += p0 + p1;
            }
            lsum += __shfl_xor_sync(0xffffffffu, lsum, 1);
            lsum += __shfl_xor_sync(0xffffffffu, lsum, 2);
            lrow[rr] = lrow[rr] * alpha + lsum;
#pragma unroll
            for (int dt = 0; dt < 8; dt++) {
                oacc[dt][rr * 2]     *= alpha;
                oacc[dt][rr * 2 + 1] *= alpha;
            }
        }

        // O += P @ V — V[s][d] tiles, B-frags via ldmatrix.trans
#pragma unroll
        for (int jc = 0; jc < 4; jc++) {
            uint32_t vf[4][4];
#pragma unroll
            for (int p = 0; p < 4; p++)
                ldsm4t(vf[p], vb + (jc * 16) * GPB + voff + p * 32);
            uint32_t af[4];
            af[0] = h2u(sacc[2 * jc    ][0], sacc[2 * jc    ][1]);
            af[1] = h2u(sacc[2 * jc    ][2], sacc[2 * jc    ][3]);
            af[2] = h2u(sacc[2 * jc + 1][0], sacc[2 * jc + 1][1]);
            af[3] = h2u(sacc[2 * jc + 1][2], sacc[2 * jc + 1][3]);
#pragma unroll
            for (int p = 0; p < 4; p++) {
                mma16(oacc[2 * p    ], af, &vf[p][0]);
                mma16(oacc[2 * p + 1], af, &vf[p][2]);
            }
        }
    }

    // normalize; write ctx fp16 in [B,S,D] layout
    const int g = lane >> 2, qq = lane & 3;
#pragma unroll
    for (int rr = 0; rr < 2; rr++) {
        float inv = 1.f / lrow[rr];
        int s = qt * 128 + warp * 16 + g + rr * 8;
        size_t base = ((size_t)(b * SEQ + s)) * D_MODEL;
#pragma unroll
        for (int dt = 0; dt < 8; dt++) {
            int d0 = h * HEAD_DIM + dt * 8 + 2 * qq;
            __half2 hv = __floats2half2_rn(oacc[dt][rr * 2] * inv,
                                           oacc[dt][rr * 2 + 1] * inv);
            *reinterpret_cast<__half2*>(g_ctx + base + d0) = hv;
        }
    }
}

// ---------------- launch -----------------------------------------------------
extern "C" void kernel_launch(void* const* d_in, const int* in_sizes, int n_in,
                              void* d_out, int out_size)
{
    const float* x     = (const float*)d_in[0];
    const float* W_qkv = (const float*)d_in[1];
    const float* b_qkv = (const float*)d_in[2];
    const float* W_out = (const float*)d_in[3];
    const float* b_out = (const float*)d_in[4];
    float* out = (float*)d_out;

    cudaFuncSetAttribute(gemm_h<0>, cudaFuncAttributeMaxDynamicSharedMemorySize, GEMM_SMEM);
    cudaFuncSetAttribute(gemm_h<1>, cudaFuncAttributeMaxDynamicSharedMemorySize, GEMM_SMEM);
    cudaFuncSetAttribute(attn_h,    cudaFuncAttributeMaxDynamicSharedMemorySize, ATTN_SMEM);

    __half* gx; __half* gwq; __half* gwo;
    cudaGetSymbolAddress((void**)&gx,  g_x);
    cudaGetSymbolAddress((void**)&gwq, g_wqkv);
    cudaGetSymbolAddress((void**)&gwo, g_wout);

    // 0) prep: round x to fp16; transpose+round weights to [N][K] fp16
    round_h<<<2048, 256>>>(x, gx, MTOK * D_MODEL / 4);
    transpose_h<<<dim3(3 * D_MODEL / 32, D_MODEL / 32), dim3(32, 8)>>>(
        W_qkv, gwq, D_MODEL, 3 * D_MODEL);
    transpose_h<<<dim3(D_MODEL / 32, D_MODEL / 32), dim3(32, 8)>>>(
        W_out, gwo, D_MODEL, D_MODEL);

    // 1) QKV projection -> g_q (pre-scaled) / g_k / g_v, all [B,H,S,Dh]
    gemm_h<0><<<dim3(3 * D_MODEL / 128, MTOK / 128), 256, GEMM_SMEM>>>(
        b_qkv, nullptr, 3 * D_MODEL, D_MODEL);

    // 2) flash attention -> ctx [B,S,D] fp16
    attn_h<<<dim3(SEQ / 128, NHEAD, BATCH), 256, ATTN_SMEM>>>();

    // 3) output projection (final fp32)
    gemm_h<1><<<dim3(D_MODEL / 128, MTOK / 128), 256, GEMM_SMEM>>>(
        b_out, out, D_MODEL, D_MODEL);
}

// round 16
// speedup vs baseline: 1.0583x; 1.0002x over previous
#include <cuda_runtime.h>
#include <cuda_fp16.h>
#include <cstdint>

#define D_MODEL 1024
#define NHEAD 16
#define HEAD_DIM 64
#define BATCH 4
#define SEQ 2048
#define MTOK (BATCH*SEQ)   // 8192

// ---------------- scratch (static device globals: allocation-free) ----------
__device__ __align__(256) __half g_q[(size_t)BATCH*NHEAD*SEQ*HEAD_DIM];   // [B,H,S,Dh] pre-scaled
__device__ __align__(256) __half g_k[(size_t)BATCH*NHEAD*SEQ*HEAD_DIM];   // [B,H,S,Dh]
__device__ __align__(256) __half g_v[(size_t)BATCH*NHEAD*SEQ*HEAD_DIM];   // [B,H,S,Dh]
__device__ __align__(256) __half g_ctx[(size_t)MTOK*D_MODEL];             // [B,S,D]
__device__ __align__(256) __half g_x[(size_t)MTOK*D_MODEL];               // [M][K]
__device__ __align__(256) __half g_wqkv[(size_t)3*D_MODEL*D_MODEL];       // [N][K] transposed
__device__ __align__(256) __half g_wout[(size_t)D_MODEL*D_MODEL];         // [N][K] transposed

// ---------------- helpers ---------------------------------------------------
__device__ __forceinline__ float ex2(float x) {
    float y;
    asm("ex2.approx.f32 %0, %1;" : "=f"(y) : "f"(x));
    return y;
}
__device__ __forceinline__ uint32_t sa(const void* p) {
    return (uint32_t)__cvta_generic_to_shared(p);
}
__device__ __forceinline__ void cpa16(uint32_t dst, const void* src) {
    asm volatile("cp.async.cg.shared.global [%0], [%1], 16;\n" :: "r"(dst), "l"(src));
}
#define CP_COMMIT asm volatile("cp.async.commit_group;\n" ::: "memory")
#define CP_WAIT1  asm volatile("cp.async.wait_group 1;\n" ::: "memory")
#define CP_WAIT0  asm volatile("cp.async.wait_group 0;\n" ::: "memory")

__device__ __forceinline__ uint32_t h2u(float a, float b) {
    __half2 h = __floats2half2_rn(a, b);
    return *reinterpret_cast<uint32_t*>(&h);
}
__device__ __forceinline__ void ldsm4(uint32_t* r, uint32_t addr) {
    asm volatile("ldmatrix.sync.aligned.m8n8.x4.shared.b16 {%0,%1,%2,%3}, [%4];"
                 : "=r"(r[0]), "=r"(r[1]), "=r"(r[2]), "=r"(r[3]) : "r"(addr));
}
__device__ __forceinline__ void ldsm4t(uint32_t* r, uint32_t addr) {
    asm volatile("ldmatrix.sync.aligned.m8n8.x4.trans.shared.b16 {%0,%1,%2,%3}, [%4];"
                 : "=r"(r[0]), "=r"(r[1]), "=r"(r[2]), "=r"(r[3]) : "r"(addr));
}

// D(16x8,f32) += A(16x16 f16,row) * B(16x8 f16,col)
__device__ __forceinline__ void mma16(float* c, const uint32_t* a, const uint32_t* b) {
    asm volatile(
        "mma.sync.aligned.m16n8k16.row.col.f32.f16.f16.f32 "
        "{%0,%1,%2,%3}, {%4,%5,%6,%7}, {%8,%9}, {%0,%1,%2,%3};\n"
        : "+f"(c[0]), "+f"(c[1]), "+f"(c[2]), "+f"(c[3])
        : "r"(a[0]), "r"(a[1]), "r"(a[2]), "r"(a[3]), "r"(b[0]), "r"(b[1]));
}

// ---------------- fused prep kernel -----------------------------------------
// One launch covers: [0,1024)   round x -> g_x (grid-stride float4)
//                    [1024,4096) transpose W_qkv tile
//                    [4096,5120) transpose W_out tile
// block = (32,8) = 256 threads for all tasks.
__global__ void prep_all(const float* __restrict__ x,
                         const float* __restrict__ Wqkv,
                         const float* __restrict__ Wout)
{
    const int bx = blockIdx.x;
    const int tx = threadIdx.x, ty = threadIdx.y;
    if (bx < 1024) {
        // task 0: round x (n4 = MTOK*D_MODEL/4 float4s)
        const int n4 = MTOK * D_MODEL / 4;
        const int tid = bx * 256 + ty * 32 + tx;
        for (int i = tid; i < n4; i += 1024 * 256) {
            float4 v = reinterpret_cast<const float4*>(x)[i];
            uint2 o = make_uint2(h2u(v.x, v.y), h2u(v.z, v.w));
            reinterpret_cast<uint2*>(g_x)[i] = o;
        }
    } else {
        const float* src; __half* dst; int Kdim, Ndim, idx, nb;
        if (bx < 4096) { src = Wqkv; dst = g_wqkv; Kdim = D_MODEL; Ndim = 3 * D_MODEL;
                         idx = bx - 1024; nb = 96; }
        else           { src = Wout; dst = g_wout; Kdim = D_MODEL; Ndim = D_MODEL;
                         idx = bx - 4096; nb = 32; }
        __shared__ __half ts[32][33];
        int n0 = (idx % nb) * 32, k0 = (idx / nb) * 32;
#pragma unroll
        for (int r = 0; r < 4; r++)
            ts[ty + 8 * r][tx] = __float2half_rn(src[(size_t)(k0 + ty + 8 * r) * Ndim + n0 + tx]);
        __syncthreads();
#pragma unroll
        for (int r = 0; r < 4; r++)
            dst[(size_t)(n0 + ty + 8 * r) * Kdim + k0 + tx] = ts[tx][ty + 8 * r];
    }
}

// ---------------- GEMM: C[M,N] = A[M,K] @ Wt[N,K]^T + bias (fp16 MMA) -------
// 128x128 CTA tile, k-tile 64, 3-stage cp.async, register-double-buffered
// ldmatrix fragments. 1-D grid with 8-wide M-group rasterization for L2 reuse.
#define GPB 144                     // smem pitch bytes (72 halves)
#define GTB (128 * GPB)             // 18432 B per operand tile
static const int GEMM_SMEM = 6 * GTB;   // 110592 B (3 stages x (A,W))

#define G_LOAD_FRAGS(AF, BF, ABASE, WBASE, KC) do {                            \
    ldsm4(AF[0], (ABASE) + (mw * 32     ) * GPB + aoff + (KC) * 32);           \
    ldsm4(AF[1], (ABASE) + (mw * 32 + 16) * GPB + aoff + (KC) * 32);           \
    ldsm4(BF[0], (WBASE) + (nw * 64     ) * GPB + boff + (KC) * 32);           \
    ldsm4(BF[1], (WBASE) + (nw * 64 + 16) * GPB + boff + (KC) * 32);           \
    ldsm4(BF[2], (WBASE) + (nw * 64 + 32) * GPB + boff + (KC) * 32);           \
    ldsm4(BF[3], (WBASE) + (nw * 64 + 48) * GPB + boff + (KC) * 32);           \
} while (0)

#define G_MMA_ALL(AF, BF) do {                                                 \
    _Pragma("unroll")                                                          \
    for (int mt = 0; mt < 2; mt++) {                                           \
        _Pragma("unroll")                                                      \
        for (int p = 0; p < 4; p++) {                                          \
            mma16(acc[mt][2 * p    ], AF[mt], &BF[p][0]);                      \
            mma16(acc[mt][2 * p + 1], AF[mt], &BF[p][2]);                      \
        }                                                                      \
    }                                                                          \
} while (0)

#define QSCALE 0.18033688011112042f   // 0.125 * log2(e)

template<int MODE>
__global__ void __launch_bounds__(256, 2)
gemm_h(const float* __restrict__ bias, float* __restrict__ C, int N, int K)
{
    extern __shared__ __align__(256) char smem[];
    const uint32_t sb = sa(smem);
    // 8-wide M-group rasterization (M/128 = 64, divisible by 8)
    const int nb = N >> 7;
    const int nig = 8 * nb;
    const int grp = blockIdx.x / nig;
    const int rem = blockIdx.x - grp * nig;
    const int m0 = ((grp << 3) + (rem & 7)) << 7;
    const int n0 = (rem >> 3) << 7;

    const int tid  = threadIdx.x;
    const int warp = tid >> 5, lane = tid & 31;
    const int mw = warp >> 1, nw = warp & 1;      // 4 x 2 warp grid, 32x64 per warp
    const int g  = lane >> 2, qq = lane & 3;

    const __half* Ag = (MODE == 1) ? g_ctx : g_x;       // [M][K]
    const __half* Wg = (MODE == 1) ? g_wout : g_wqkv;   // [N][K]

    float acc[2][8][4];
#pragma unroll
    for (int i = 0; i < 2; i++)
#pragma unroll
        for (int j = 0; j < 8; j++)
#pragma unroll
            for (int r = 0; r < 4; r++) acc[i][j][r] = 0.f;

    const int lrow = tid >> 1;             // 128 rows, 2 threads/row
    const int lh   = (tid & 1) * 32;       // halves offset within row
    auto load_tiles = [&](int kt, int s) {
        const __half* As = Ag + (size_t)(m0 + lrow) * K + kt * 64 + lh;
        const __half* Ws = Wg + (size_t)(n0 + lrow) * K + kt * 64 + lh;
        uint32_t ab = sb + s * 2 * GTB;
        uint32_t wb = ab + GTB;
        uint32_t off = lrow * GPB + lh * 2;
#pragma unroll
        for (int j = 0; j < 4; j++) {
            cpa16(ab + off + j * 16, As + j * 8);
            cpa16(wb + off + j * 16, Ws + j * 8);
        }
        CP_COMMIT;
    };

    // per-lane ldmatrix byte offsets within a tile
    const uint32_t aoff = (uint32_t)((lane & 15) * GPB + (lane >> 4) * 16);
    const uint32_t boff = (uint32_t)(((lane & 7) + ((lane >> 4) << 3)) * GPB
                                     + ((lane >> 3) & 1) * 16);

    uint32_t af0[2][4], bf0[4][4], af1[2][4], bf1[4][4];

    const int NT = K >> 6;   // k-tiles of 64
    load_tiles(0, 0);
    load_tiles(1, 1);
    CP_WAIT1;
    __syncthreads();
    G_LOAD_FRAGS(af0, bf0, sb, sb + GTB, 0);

    for (int kt = 0; kt < NT; kt++) {
        const int s = kt % 3;
        const uint32_t cab = sb + s * 2 * GTB;
        const uint32_t cwb = cab + GTB;

        G_LOAD_FRAGS(af1, bf1, cab, cwb, 1);
        if (kt + 2 < NT) load_tiles(kt + 2, (kt + 2) % 3);
        G_MMA_ALL(af0, bf0);

        G_LOAD_FRAGS(af0, bf0, cab, cwb, 2);
        G_MMA_ALL(af1, bf1);

        G_LOAD_FRAGS(af1, bf1, cab, cwb, 3);
        G_MMA_ALL(af0, bf0);

        if (kt + 1 < NT) {
            if (kt + 2 < NT) { CP_WAIT1; } else { CP_WAIT0; }  // full drain before final tile
            __syncthreads();
            const uint32_t nab = sb + ((kt + 1) % 3) * 2 * GTB;
            G_LOAD_FRAGS(af0, bf0, nab, nab + GTB, 0);
        }
        G_MMA_ALL(af1, bf1);
    }

    // epilogue — Q/K/V all coalesced half2 stores ([B,H,S,Dh])
#pragma unroll
    for (int mt = 0; mt < 2; mt++) {
#pragma unroll
        for (int nt = 0; nt < 8; nt++) {
            int col = n0 + nw * 64 + nt * 8 + 2 * qq;
            float b0 = __ldg(bias + col), b1 = __ldg(bias + col + 1);
#pragma unroll
            for (int half = 0; half < 2; half++) {
                int row = m0 + mw * 32 + mt * 16 + g + half * 8;
                float v0 = acc[mt][nt][half * 2    ] + b0;
                float v1 = acc[mt][nt][half * 2 + 1] + b1;
                if (MODE == 0) {
                    int c = col >> 10;            // 0:q 1:k 2:v
                    int h = (col >> 6) & 15;
                    int d = col & 63;
                    int b = row >> 11;
                    int s = row & 2047;
                    if (c == 0) { v0 *= QSCALE; v1 *= QSCALE; }   // fold softmax scale into Q
                    size_t idx = ((size_t)((b * NHEAD + h) * SEQ + s)) * HEAD_DIM + d;
                    __half* dst = (c == 0) ? g_q : (c == 1) ? g_k : g_v;
                    __half2 hv = __floats2half2_rn(v0, v1);
                    *reinterpret_cast<__half2*>(dst + idx) = hv;
                } else {
                    *reinterpret_cast<float2*>(C + (size_t)row * N + col) =
                        make_float2(v0, v1);
                }
            }
        }
    }
}

// ---------------- flash attention (fp16 MMA, trans-ldsm PV) -----------------
// grid: (S/128, H, B); block 256 (8 warps, 16 query rows each).
#define QTB (128 * GPB)             // 18432 B
#define KTB (64 * GPB)              // 9216 B
#define SK_OFF(s) (QTB + (s) * KTB)
#define SV_OFF(s) (QTB + 3 * KTB + (s) * KTB)
static const int ATTN_SMEM = QTB + 6 * KTB;   // 73728 B

#define A_LOADB(BF, BASE, KC) do {                                             \
    ldsm4(BF[0], (BASE) + ( 0) * GPB + boff + (KC) * 32);                      \
    ldsm4(BF[1], (BASE) + (16) * GPB + boff + (KC) * 32);                      \
    ldsm4(BF[2], (BASE) + (32) * GPB + boff + (KC) * 32);                      \
    ldsm4(BF[3], (BASE) + (48) * GPB + boff + (KC) * 32);                      \
} while (0)

#define A_MMA_S(QF, KF) do {                                                   \
    _Pragma("unroll")                                                          \
    for (int p = 0; p < 4; p++) {                                              \
        mma16(sacc[2 * p    ], QF, &KF[p][0]);                                 \
        mma16(sacc[2 * p + 1], QF, &KF[p][2]);                                 \
    }                                                                          \
} while (0)

__global__ void __launch_bounds__(256, 2)
attn_h()
{
    extern __shared__ __align__(256) char smem[];
    const uint32_t sb = sa(smem);

    const int tid = threadIdx.x, warp = tid >> 5, lane = tid & 31;

    const int qt = blockIdx.x, h = blockIdx.y, b = blockIdx.z;
    const size_t head_off = ((size_t)(b * NHEAD + h)) * SEQ * HEAD_DIM;
    const __half* Qg = g_q + head_off;
    const __half* Kg = g_k + head_off;
    const __half* Vg = g_v + head_off;   // [S][Dh]

    // K/V loaders: 64 rows x 128B, 4 threads/row (identical layouts)
    const int kvrow = tid >> 2;
    const int kvq = (tid & 3) * 16;      // halves offset
    auto load_kv = [&](int kt, int s) {
        const __half* Ks = Kg + (size_t)(kt * 64 + kvrow) * HEAD_DIM + kvq;
        const __half* Vs = Vg + (size_t)(kt * 64 + kvrow) * HEAD_DIM + kvq;
        uint32_t kb = sb + SK_OFF(s) + kvrow * GPB + kvq * 2;
        uint32_t vb = sb + SV_OFF(s) + kvrow * GPB + kvq * 2;
#pragma unroll
        for (int j = 0; j < 2; j++) {
            cpa16(kb + j * 16, Ks + j * 8);
            cpa16(vb + j * 16, Vs + j * 8);
        }
        CP_COMMIT;
    };

    // Q: 128 rows x 128B, 2 threads/row (committed with kv tile 0)
    {
        const int qrow = tid >> 1;
        const int qh = (tid & 1) * 32;
        const __half* Qs = Qg + (size_t)(qt * 128 + qrow) * HEAD_DIM + qh;
        uint32_t qb = sb + qrow * GPB + qh * 2;
#pragma unroll
        for (int j = 0; j < 4; j++)
            cpa16(qb + j * 16, Qs + j * 8);
    }
    load_kv(0, 0);
    load_kv(1, 1);

    // ldmatrix per-lane offsets
    const uint32_t aoff = (uint32_t)((lane & 15) * GPB + (lane >> 4) * 16);
    const uint32_t boff = (uint32_t)(((lane & 7) + ((lane >> 4) << 3)) * GPB
                                     + ((lane >> 3) & 1) * 16);

    float oacc[8][4];
#pragma unroll
    for (int i = 0; i < 8; i++)
#pragma unroll
        for (int r = 0; r < 4; r++) oacc[i][r] = 0.f;
    float mrow[2] = {-1e30f, -1e30f};
    float lrow[2] = {0.f, 0.f};

    uint32_t qf[4][4];   // hoisted Q fragments (k-tile invariant; Q pre-scaled)
    uint32_t kf0[4][4], kf1[4][4];

    const int NT = SEQ / 64;
    for (int kt = 0; kt < NT; kt++) {
        if (kt + 1 < NT) { CP_WAIT1; } else { CP_WAIT0; }   // full drain on last tile
        __syncthreads();

        if (kt == 0) {
#pragma unroll
            for (int kc = 0; kc < 4; kc++)
                ldsm4(qf[kc], sb + (warp * 16) * GPB + aoff + kc * 32);
        }

        const int s = kt % 3;
        const uint32_t kb = sb + SK_OFF(s);
        const uint32_t vb = sb + SV_OFF(s);

        // S = Q K^T (16 x 64 per warp), K fragments double-buffered
        float sacc[8][4];
#pragma unroll
        for (int i = 0; i < 8; i++)
#pragma unroll
            for (int r = 0; r < 4; r++) sacc[i][r] = 0.f;

        A_LOADB(kf0, kb, 0);
        A_LOADB(kf1, kb, 1);
        // gmem prefetch issued EARLY (stage (kt+2)%3 freed by this iter's barrier)
        if (kt + 2 < NT) load_kv(kt + 2, (kt + 2) % 3);
        A_MMA_S(qf[0], kf0);
        A_LOADB(kf0, kb, 2);
        A_MMA_S(qf[1], kf1);
        A_LOADB(kf1, kb, 3);
        A_MMA_S(qf[2], kf0);
        A_MMA_S(qf[3], kf1);

        // online softmax in log2 domain (scores pre-scaled via Q)
#pragma unroll
        for (int rr = 0; rr < 2; rr++) {
            float mloc = -1e30f;
#pragma unroll
            for (int nt = 0; nt < 8; nt++)
                mloc = fmaxf(mloc, fmaxf(sacc[nt][rr * 2], sacc[nt][rr * 2 + 1]));
            mloc = fmaxf(mloc, __shfl_xor_sync(0xffffffffu, mloc, 1));
            mloc = fmaxf(mloc, __shfl_xor_sync(0xffffffffu, mloc, 2));
            float mnew  = fmaxf(mrow[rr], mloc);
            float alpha = ex2(mrow[rr] - mnew);
            mrow[rr] = mnew;
            float lsum = 0.f;
#pragma unroll
            for (int nt = 0; nt < 8; nt++) {
                float p0 = ex2(sacc[nt][rr * 2]     - mnew);
                float p1 = ex2(sacc[nt][rr * 2 + 1] - mnew);
                sacc[nt][rr * 2] = p0; sacc[nt][rr * 2 + 1] = p1;
                lsum += p0 + p1;
            }
            lsum += __shfl_xor_sync(0xffffffffu, lsum, 1);
            lsum += __shfl_xor_sync(0xffffffffu, lsum, 2);
            lrow[rr] = lrow[rr] * alpha + lsum;
#pragma unroll
            for (int dt = 0; dt < 8; dt++) {
                oacc[dt][rr * 2]     *= alpha;
                oacc[dt][rr * 2 + 1] *= alpha;
            }
        }

        // O += P @ V — V[s][d] tiles, B-frags via ldmatrix.trans
#pragma unroll
        for (int jc = 0; jc < 4; jc++) {
            uint32_t vf[4][4];
#pragma unroll
            for (int p = 0; p < 4; p++)
                ldsm4t(vf[p], vb + (jc * 16) * GPB + aoff + p * 32);
            uint32_t af[4];
            af[0] = h2u(sacc[2 * jc    ][0], sacc[2 * jc    ][1]);
            af[1] = h2u(sacc[2 * jc    ][2], sacc[2 * jc    ][3]);
            af[2] = h2u(sacc[2 * jc + 1][0], sacc[2 * jc + 1][1]);
            af[3] = h2u(sacc[2 * jc + 1][2], sacc[2 * jc + 1][3]);
#pragma unroll
            for (int p = 0; p < 4; p++) {
                mma16(oacc[2 * p    ], af, &vf[p][0]);
                mma16(oacc[2 * p + 1], af, &vf[p][2]);
            }
        }
    }

    // normalize; write ctx fp16 in [B,S,D] layout
    const int g = lane >> 2, qq = lane & 3;
#pragma unroll
    for (int rr = 0; rr < 2; rr++) {
        float inv = 1.f / lrow[rr];
        int s = qt * 128 + warp * 16 + g + rr * 8;
        size_t base = ((size_t)(b * SEQ + s)) * D_MODEL;
#pragma unroll
        for (int dt = 0; dt < 8; dt++) {
            int d0 = h * HEAD_DIM + dt * 8 + 2 * qq;
            __half2 hv = __floats2half2_rn(oacc[dt][rr * 2] * inv,
                                           oacc[dt][rr * 2 + 1] * inv);
            *reinterpret_cast<__half2*>(g_ctx + base + d0) = hv;
        }
    }
}

// ---------------- launch -----------------------------------------------------
extern "C" void kernel_launch(void* const* d_in, const int* in_sizes, int n_in,
                              void* d_out, int out_size)
{
    const float* x     = (const float*)d_in[0];
    const float* W_qkv = (const float*)d_in[1];
    const float* b_qkv = (const float*)d_in[2];
    const float* W_out = (const float*)d_in[3];
    const float* b_out = (const float*)d_in[4];
    float* out = (float*)d_out;

    cudaFuncSetAttribute(gemm_h<0>, cudaFuncAttributeMaxDynamicSharedMemorySize, GEMM_SMEM);
    cudaFuncSetAttribute(gemm_h<1>, cudaFuncAttributeMaxDynamicSharedMemorySize, GEMM_SMEM);
    cudaFuncSetAttribute(attn_h,    cudaFuncAttributeMaxDynamicSharedMemorySize, ATTN_SMEM);

    // 0) fused prep: round x + transpose both weight matrices (one launch)
    prep_all<<<5120, dim3(32, 8)>>>(x, W_qkv, W_out);

    // 1) QKV projection -> g_q (pre-scaled) / g_k / g_v, all [B,H,S,Dh]
    gemm_h<0><<<(3 * D_MODEL / 128) * (MTOK / 128), 256, GEMM_SMEM>>>(
        b_qkv, nullptr, 3 * D_MODEL, D_MODEL);

    // 2) flash attention -> ctx [B,S,D] fp16
    attn_h<<<dim3(SEQ / 128, NHEAD, BATCH), 256, ATTN_SMEM>>>();

    // 3) output projection (final fp32)
    gemm_h<1><<<(D_MODEL / 128) * (MTOK / 128), 256, GEMM_SMEM>>>(
        b_out, out, D_MODEL, D_MODEL);
}

// round 17
// speedup vs baseline: 1.0625x; 1.0040x over previous
#include <cuda_runtime.h>
#include <cuda_fp16.h>
#include <cstdint>

#define D_MODEL 1024
#define NHEAD 16
#define HEAD_DIM 64
#define BATCH 4
#define SEQ 2048
#define MTOK (BATCH*SEQ)   // 8192

// ---------------- scratch (static device globals: allocation-free) ----------
__device__ __align__(256) __half g_q[(size_t)BATCH*NHEAD*SEQ*HEAD_DIM];   // [B,H,S,Dh] pre-scaled
__device__ __align__(256) __half g_k[(size_t)BATCH*NHEAD*SEQ*HEAD_DIM];   // [B,H,S,Dh]
__device__ __align__(256) __half g_v[(size_t)BATCH*NHEAD*SEQ*HEAD_DIM];   // [B,H,S,Dh]
__device__ __align__(256) __half g_ctx[(size_t)MTOK*D_MODEL];             // [B,S,D]
__device__ __align__(256) __half g_x[(size_t)MTOK*D_MODEL];               // [M][K]
__device__ __align__(256) __half g_wqkv[(size_t)3*D_MODEL*D_MODEL];       // [N][K] transposed
__device__ __align__(256) __half g_wout[(size_t)D_MODEL*D_MODEL];         // [N][K] transposed

// ---------------- helpers ---------------------------------------------------
__device__ __forceinline__ float ex2(float x) {
    float y;
    asm("ex2.approx.f32 %0, %1;" : "=f"(y) : "f"(x));
    return y;
}
__device__ __forceinline__ uint32_t sa(const void* p) {
    return (uint32_t)__cvta_generic_to_shared(p);
}
__device__ __forceinline__ void cpa16(uint32_t dst, const void* src) {
    asm volatile("cp.async.cg.shared.global [%0], [%1], 16;\n" :: "r"(dst), "l"(src));
}
#define CP_COMMIT asm volatile("cp.async.commit_group;\n" ::: "memory")
#define CP_WAIT2  asm volatile("cp.async.wait_group 2;\n" ::: "memory")
#define CP_WAIT1  asm volatile("cp.async.wait_group 1;\n" ::: "memory")
#define CP_WAIT0  asm volatile("cp.async.wait_group 0;\n" ::: "memory")

__device__ __forceinline__ uint32_t h2u(float a, float b) {
    __half2 h = __floats2half2_rn(a, b);
    return *reinterpret_cast<uint32_t*>(&h);
}
__device__ __forceinline__ void ldsm4(uint32_t* r, uint32_t addr) {
    asm volatile("ldmatrix.sync.aligned.m8n8.x4.shared.b16 {%0,%1,%2,%3}, [%4];"
                 : "=r"(r[0]), "=r"(r[1]), "=r"(r[2]), "=r"(r[3]) : "r"(addr));
}
__device__ __forceinline__ void ldsm4t(uint32_t* r, uint32_t addr) {
    asm volatile("ldmatrix.sync.aligned.m8n8.x4.trans.shared.b16 {%0,%1,%2,%3}, [%4];"
                 : "=r"(r[0]), "=r"(r[1]), "=r"(r[2]), "=r"(r[3]) : "r"(addr));
}

// D(16x8,f32) += A(16x16 f16,row) * B(16x8 f16,col)
__device__ __forceinline__ void mma16(float* c, const uint32_t* a, const uint32_t* b) {
    asm volatile(
        "mma.sync.aligned.m16n8k16.row.col.f32.f16.f16.f32 "
        "{%0,%1,%2,%3}, {%4,%5,%6,%7}, {%8,%9}, {%0,%1,%2,%3};\n"
        : "+f"(c[0]), "+f"(c[1]), "+f"(c[2]), "+f"(c[3])
        : "r"(a[0]), "r"(a[1]), "r"(a[2]), "r"(a[3]), "r"(b[0]), "r"(b[1]));
}

// ---------------- fused prep kernel -----------------------------------------
__global__ void prep_all(const float* __restrict__ x,
                         const float* __restrict__ Wqkv,
                         const float* __restrict__ Wout)
{
    const int bx = blockIdx.x;
    const int tx = threadIdx.x, ty = threadIdx.y;
    if (bx < 1024) {
        const int n4 = MTOK * D_MODEL / 4;
        const int tid = bx * 256 + ty * 32 + tx;
        for (int i = tid; i < n4; i += 1024 * 256) {
            float4 v = reinterpret_cast<const float4*>(x)[i];
            uint2 o = make_uint2(h2u(v.x, v.y), h2u(v.z, v.w));
            reinterpret_cast<uint2*>(g_x)[i] = o;
        }
    } else {
        const float* src; __half* dst; int Kdim, Ndim, idx, nb;
        if (bx < 4096) { src = Wqkv; dst = g_wqkv; Kdim = D_MODEL; Ndim = 3 * D_MODEL;
                         idx = bx - 1024; nb = 96; }
        else           { src = Wout; dst = g_wout; Kdim = D_MODEL; Ndim = D_MODEL;
                         idx = bx - 4096; nb = 32; }
        __shared__ __half ts[32][33];
        int n0 = (idx % nb) * 32, k0 = (idx / nb) * 32;
#pragma unroll
        for (int r = 0; r < 4; r++)
            ts[ty + 8 * r][tx] = __float2half_rn(src[(size_t)(k0 + ty + 8 * r) * Ndim + n0 + tx]);
        __syncthreads();
#pragma unroll
        for (int r = 0; r < 4; r++)
            dst[(size_t)(n0 + ty + 8 * r) * Kdim + k0 + tx] = ts[tx][ty + 8 * r];
    }
}

// ---------------- GEMM: C[M,N] = A[M,K] @ Wt[N,K]^T + bias (fp16 MMA) -------
// 128x128 CTA tile, k-tile 64, 3-stage cp.async, register-double-buffered
// ldmatrix fragments. 1-D grid with 8-wide M-group rasterization.
#define GPB 144                     // smem pitch bytes (72 halves)
#define GTB (128 * GPB)             // 18432 B per operand tile
static const int GEMM_SMEM = 6 * GTB;   // 110592 B (3 stages x (A,W))

#define G_LOAD_FRAGS(AF, BF, ABASE, WBASE, KC) do {                            \
    ldsm4(AF[0], (ABASE) + (mw * 32     ) * GPB + aoff + (KC) * 32);           \
    ldsm4(AF[1], (ABASE) + (mw * 32 + 16) * GPB + aoff + (KC) * 32);           \
    ldsm4(BF[0], (WBASE) + (nw * 64     ) * GPB + boff + (KC) * 32);           \
    ldsm4(BF[1], (WBASE) + (nw * 64 + 16) * GPB + boff + (KC) * 32);           \
    ldsm4(BF[2], (WBASE) + (nw * 64 + 32) * GPB + boff + (KC) * 32);           \
    ldsm4(BF[3], (WBASE) + (nw * 64 + 48) * GPB + boff + (KC) * 32);           \
} while (0)

#define G_MMA_ALL(AF, BF) do {                                                 \
    _Pragma("unroll")                                                          \
    for (int mt = 0; mt < 2; mt++) {                                           \
        _Pragma("unroll")                                                      \
        for (int p = 0; p < 4; p++) {                                          \
            mma16(acc[mt][2 * p    ], AF[mt], &BF[p][0]);                      \
            mma16(acc[mt][2 * p + 1], AF[mt], &BF[p][2]);                      \
        }                                                                      \
    }                                                                          \
} while (0)

#define QSCALE 0.18033688011112042f   // 0.125 * log2(e)

template<int MODE>
__global__ void __launch_bounds__(256, 2)
gemm_h(const float* __restrict__ bias, float* __restrict__ C, int N, int K)
{
    extern __shared__ __align__(256) char smem[];
    const uint32_t sb = sa(smem);
    const int nb = N >> 7;
    const int nig = 8 * nb;
    const int grp = blockIdx.x / nig;
    const int rem = blockIdx.x - grp * nig;
    const int m0 = ((grp << 3) + (rem & 7)) << 7;
    const int n0 = (rem >> 3) << 7;

    const int tid  = threadIdx.x;
    const int warp = tid >> 5, lane = tid & 31;
    const int mw = warp >> 1, nw = warp & 1;      // 4 x 2 warp grid, 32x64 per warp
    const int g  = lane >> 2, qq = lane & 3;

    const __half* Ag = (MODE == 1) ? g_ctx : g_x;       // [M][K]
    const __half* Wg = (MODE == 1) ? g_wout : g_wqkv;   // [N][K]

    float acc[2][8][4];
#pragma unroll
    for (int i = 0; i < 2; i++)
#pragma unroll
        for (int j = 0; j < 8; j++)
#pragma unroll
            for (int r = 0; r < 4; r++) acc[i][j][r] = 0.f;

    const int lrow = tid >> 1;             // 128 rows, 2 threads/row
    const int lh   = (tid & 1) * 32;       // halves offset within row
    auto load_tiles = [&](int kt, int s) {
        const __half* As = Ag + (size_t)(m0 + lrow) * K + kt * 64 + lh;
        const __half* Ws = Wg + (size_t)(n0 + lrow) * K + kt * 64 + lh;
        uint32_t ab = sb + s * 2 * GTB;
        uint32_t wb = ab + GTB;
        uint32_t off = lrow * GPB + lh * 2;
#pragma unroll
        for (int j = 0; j < 4; j++) {
            cpa16(ab + off + j * 16, As + j * 8);
            cpa16(wb + off + j * 16, Ws + j * 8);
        }
        CP_COMMIT;
    };

    const uint32_t aoff = (uint32_t)((lane & 15) * GPB + (lane >> 4) * 16);
    const uint32_t boff = (uint32_t)(((lane & 7) + ((lane >> 4) << 3)) * GPB
                                     + ((lane >> 3) & 1) * 16);

    uint32_t af0[2][4], bf0[4][4], af1[2][4], bf1[4][4];

    const int NT = K >> 6;   // k-tiles of 64
    load_tiles(0, 0);
    load_tiles(1, 1);
    CP_WAIT1;
    __syncthreads();
    G_LOAD_FRAGS(af0, bf0, sb, sb + GTB, 0);

    for (int kt = 0; kt < NT; kt++) {
        const int s = kt % 3;
        const uint32_t cab = sb + s * 2 * GTB;
        const uint32_t cwb = cab + GTB;

        G_LOAD_FRAGS(af1, bf1, cab, cwb, 1);
        if (kt + 2 < NT) load_tiles(kt + 2, (kt + 2) % 3);
        G_MMA_ALL(af0, bf0);

        G_LOAD_FRAGS(af0, bf0, cab, cwb, 2);
        G_MMA_ALL(af1, bf1);

        G_LOAD_FRAGS(af1, bf1, cab, cwb, 3);
        G_MMA_ALL(af0, bf0);

        if (kt + 1 < NT) {
            if (kt + 2 < NT) { CP_WAIT1; } else { CP_WAIT0; }  // full drain before final tile
            __syncthreads();
            const uint32_t nab = sb + ((kt + 1) % 3) * 2 * GTB;
            G_LOAD_FRAGS(af0, bf0, nab, nab + GTB, 0);
        }
        G_MMA_ALL(af1, bf1);
    }

    // epilogue — Q/K/V all coalesced half2 stores ([B,H,S,Dh])
#pragma unroll
    for (int mt = 0; mt < 2; mt++) {
#pragma unroll
        for (int nt = 0; nt < 8; nt++) {
            int col = n0 + nw * 64 + nt * 8 + 2 * qq;
            float b0 = __ldg(bias + col), b1 = __ldg(bias + col + 1);
#pragma unroll
            for (int half = 0; half < 2; half++) {
                int row = m0 + mw * 32 + mt * 16 + g + half * 8;
                float v0 = acc[mt][nt][half * 2    ] + b0;
                float v1 = acc[mt][nt][half * 2 + 1] + b1;
                if (MODE == 0) {
                    int c = col >> 10;            // 0:q 1:k 2:v
                    int h = (col >> 6) & 15;
                    int d = col & 63;
                    int b = row >> 11;
                    int s = row & 2047;
                    if (c == 0) { v0 *= QSCALE; v1 *= QSCALE; }   // fold softmax scale into Q
                    size_t idx = ((size_t)((b * NHEAD + h) * SEQ + s)) * HEAD_DIM + d;
                    __half* dst = (c == 0) ? g_q : (c == 1) ? g_k : g_v;
                    __half2 hv = __floats2half2_rn(v0, v1);
                    *reinterpret_cast<__half2*>(dst + idx) = hv;
                } else {
                    *reinterpret_cast<float2*>(C + (size_t)row * N + col) =
                        make_float2(v0, v1);
                }
            }
        }
    }
}

// ---------------- flash attention (fp16 MMA, 4-stage KV pipeline) -----------
// grid: (S/128, H, B); block 256 (8 warps, 16 query rows each).
#define QTB (128 * GPB)             // 18432 B
#define KTB (64 * GPB)              // 9216 B
#define SK_OFF(s) (QTB + (s) * KTB)
#define SV_OFF(s) (QTB + 4 * KTB + (s) * KTB)
static const int ATTN_SMEM = QTB + 8 * KTB;   // 92160 B (4 stages)

#define A_LOADB(BF, BASE, KC) do {                                             \
    ldsm4(BF[0], (BASE) + ( 0) * GPB + boff + (KC) * 32);                      \
    ldsm4(BF[1], (BASE) + (16) * GPB + boff + (KC) * 32);                      \
    ldsm4(BF[2], (BASE) + (32) * GPB + boff + (KC) * 32);                      \
    ldsm4(BF[3], (BASE) + (48) * GPB + boff + (KC) * 32);                      \
} while (0)

#define A_MMA_S(QF, KF) do {                                                   \
    _Pragma("unroll")                                                          \
    for (int p = 0; p < 4; p++) {                                              \
        mma16(sacc[2 * p    ], QF, &KF[p][0]);                                 \
        mma16(sacc[2 * p + 1], QF, &KF[p][2]);                                 \
    }                                                                          \
} while (0)

__global__ void __launch_bounds__(256, 2)
attn_h()
{
    extern __shared__ __align__(256) char smem[];
    const uint32_t sb = sa(smem);

    const int tid = threadIdx.x, warp = tid >> 5, lane = tid & 31;

    const int qt = blockIdx.x, h = blockIdx.y, b = blockIdx.z;
    const size_t head_off = ((size_t)(b * NHEAD + h)) * SEQ * HEAD_DIM;
    const __half* Qg = g_q + head_off;
    const __half* Kg = g_k + head_off;
    const __half* Vg = g_v + head_off;   // [S][Dh]

    // K/V loaders: 64 rows x 128B, 4 threads/row
    const int kvrow = tid >> 2;
    const int kvq = (tid & 3) * 16;      // halves offset
    auto load_kv = [&](int kt, int s) {
        const __half* Ks = Kg + (size_t)(kt * 64 + kvrow) * HEAD_DIM + kvq;
        const __half* Vs = Vg + (size_t)(kt * 64 + kvrow) * HEAD_DIM + kvq;
        uint32_t kb = sb + SK_OFF(s) + kvrow * GPB + kvq * 2;
        uint32_t vb = sb + SV_OFF(s) + kvrow * GPB + kvq * 2;
#pragma unroll
        for (int j = 0; j < 2; j++) {
            cpa16(kb + j * 16, Ks + j * 8);
            cpa16(vb + j * 16, Vs + j * 8);
        }
        CP_COMMIT;
    };

    // Q: 128 rows x 128B, 2 threads/row (committed with kv tile 0)
    {
        const int qrow = tid >> 1;
        const int qh = (tid & 1) * 32;
        const __half* Qs = Qg + (size_t)(qt * 128 + qrow) * HEAD_DIM + qh;
        uint32_t qb = sb + qrow * GPB + qh * 2;
#pragma unroll
        for (int j = 0; j < 4; j++)
            cpa16(qb + j * 16, Qs + j * 8);
    }
    load_kv(0, 0);     // group 0 (includes Q)
    load_kv(1, 1);     // group 1
    load_kv(2, 2);     // group 2

    // ldmatrix per-lane offsets
    const uint32_t aoff = (uint32_t)((lane & 15) * GPB + (lane >> 4) * 16);
    const uint32_t boff = (uint32_t)(((lane & 7) + ((lane >> 4) << 3)) * GPB
                                     + ((lane >> 3) & 1) * 16);

    float oacc[8][4];
#pragma unroll
    for (int i = 0; i < 8; i++)
#pragma unroll
        for (int r = 0; r < 4; r++) oacc[i][r] = 0.f;
    float mrow[2] = {-1e30f, -1e30f};
    float lrow[2] = {0.f, 0.f};

    uint32_t qf[4][4];   // hoisted Q fragments (k-tile invariant; Q pre-scaled)
    uint32_t kf0[4][4], kf1[4][4];

    const int NT = SEQ / 64;
    for (int kt = 0; kt < NT; kt++) {
        // graduated drain: retire group kt (outstanding = kt..min(kt+2,NT-1))
        if (kt + 2 < NT)      { CP_WAIT2; }
        else if (kt + 1 < NT) { CP_WAIT1; }
        else                  { CP_WAIT0; }
        __syncthreads();

        if (kt == 0) {
#pragma unroll
            for (int kc = 0; kc < 4; kc++)
                ldsm4(qf[kc], sb + (warp * 16) * GPB + aoff + kc * 32);
        }

        const int s = kt & 3;
        const uint32_t kb = sb + SK_OFF(s);
        const uint32_t vb = sb + SV_OFF(s);

        // S = Q K^T (16 x 64 per warp), K fragments double-buffered
        float sacc[8][4];
#pragma unroll
        for (int i = 0; i < 8; i++)
#pragma unroll
            for (int r = 0; r < 4; r++) sacc[i][r] = 0.f;

        A_LOADB(kf0, kb, 0);
        A_LOADB(kf1, kb, 1);
        // prefetch kt+3 into stage (kt+3)&3 = (kt-1)&3 (freed by this iter's barrier)
        if (kt + 3 < NT) load_kv(kt + 3, (kt + 3) & 3);
        A_MMA_S(qf[0], kf0);
        A_LOADB(kf0, kb, 2);
        A_MMA_S(qf[1], kf1);
        A_LOADB(kf1, kb, 3);
        A_MMA_S(qf[2], kf0);
        A_MMA_S(qf[3], kf1);

        // online softmax in log2 domain (scores pre-scaled via Q)
#pragma unroll
        for (int rr = 0; rr < 2; rr++) {
            float mloc = -1e30f;
#pragma unroll
            for (int nt = 0; nt < 8; nt++)
                mloc = fmaxf(mloc, fmaxf(sacc[nt][rr * 2], sacc[nt][rr * 2 + 1]));
            mloc = fmaxf(mloc, __shfl_xor_sync(0xffffffffu, mloc, 1));
            mloc = fmaxf(mloc, __shfl_xor_sync(0xffffffffu, mloc, 2));
            float mnew  = fmaxf(mrow[rr], mloc);
            float alpha = ex2(mrow[rr] - mnew);
            mrow[rr] = mnew;
            float lsum = 0.f;
#pragma unroll
            for (int nt = 0; nt < 8; nt++) {
                float p0 = ex2(sacc[nt][rr * 2]     - mnew);
                float p1 = ex2(sacc[nt][rr * 2 + 1] - mnew);
                sacc[nt][rr * 2] = p0; sacc[nt][rr * 2 + 1] = p1;
                lsum += p0 + p1;
            }
            lsum += __shfl_xor_sync(0xffffffffu, lsum, 1);
            lsum += __shfl_xor_sync(0xffffffffu, lsum, 2);
            lrow[rr] = lrow[rr] * alpha + lsum;
#pragma unroll
            for (int dt = 0; dt < 8; dt++) {
                oacc[dt][rr * 2]     *= alpha;
                oacc[dt][rr * 2 + 1] *= alpha;
            }
        }

        // O += P @ V — V[s][d] tiles, B-frags via ldmatrix.trans
#pragma unroll
        for (int jc = 0; jc < 4; jc++) {
            uint32_t vf[4][4];
#pragma unroll
            for (int p = 0; p < 4; p++)
                ldsm4t(vf[p], vb + (jc * 16) * GPB + aoff + p * 32);
            uint32_t af[4];
            af[0] = h2u(sacc[2 * jc    ][0], sacc[2 * jc    ][1]);
            af[1] = h2u(sacc[2 * jc    ][2], sacc[2 * jc    ][3]);
            af[2] = h2u(sacc[2 * jc + 1][0], sacc[2 * jc + 1][1]);
            af[3] = h2u(sacc[2 * jc + 1][2], sacc[2 * jc + 1][3]);
#pragma unroll
            for (int p = 0; p < 4; p++) {
                mma16(oacc[2 * p    ], af, &vf[p][0]);
                mma16(oacc[2 * p + 1], af, &vf[p][2]);
            }
        }
    }

    // normalize; write ctx fp16 in [B,S,D] layout
    const int g = lane >> 2, qq = lane & 3;
#pragma unroll
    for (int rr = 0; rr < 2; rr++) {
        float inv = 1.f / lrow[rr];
        int s = qt * 128 + warp * 16 + g + rr * 8;
        size_t base = ((size_t)(b * SEQ + s)) * D_MODEL;
#pragma unroll
        for (int dt = 0; dt < 8; dt++) {
            int d0 = h * HEAD_DIM + dt * 8 + 2 * qq;
            __half2 hv = __floats2half2_rn(oacc[dt][rr * 2] * inv,
                                           oacc[dt][rr * 2 + 1] * inv);
            *reinterpret_cast<__half2*>(g_ctx + base + d0) = hv;
        }
    }
}

// ---------------- launch -----------------------------------------------------
extern "C" void kernel_launch(void* const* d_in, const int* in_sizes, int n_in,
                              void* d_out, int out_size)
{
    const float* x     = (const float*)d_in[0];
    const float* W_qkv = (const float*)d_in[1];
    const float* b_qkv = (const float*)d_in[2];
    const float* W_out = (const float*)d_in[3];
    const float* b_out = (const float*)d_in[4];
    float* out = (float*)d_out;

    cudaFuncSetAttribute(gemm_h<0>, cudaFuncAttributeMaxDynamicSharedMemorySize, GEMM_SMEM);
    cudaFuncSetAttribute(gemm_h<1>, cudaFuncAttributeMaxDynamicSharedMemorySize, GEMM_SMEM);
    cudaFuncSetAttribute(attn_h,    cudaFuncAttributeMaxDynamicSharedMemorySize, ATTN_SMEM);

    // 0) fused prep: round x + transpose both weight matrices (one launch)
    prep_all<<<5120, dim3(32, 8)>>>(x, W_qkv, W_out);

    // 1) QKV projection -> g_q (pre-scaled) / g_k / g_v, all [B,H,S,Dh]
    gemm_h<0><<<(3 * D_MODEL / 128) * (MTOK / 128), 256, GEMM_SMEM>>>(
        b_qkv, nullptr, 3 * D_MODEL, D_MODEL);

    // 2) flash attention -> ctx [B,S,D] fp16
    attn_h<<<dim3(SEQ / 128, NHEAD, BATCH), 256, ATTN_SMEM>>>();

    // 3) output projection (final fp32)
    gemm_h<1><<<(D_MODEL / 128) * (MTOK / 128), 256, GEMM_SMEM>>>(
        b_out, out, D_MODEL, D_MODEL);
}